// round 2
// baseline (speedup 1.0000x reference)
#include <cuda_runtime.h>
#include <math.h>
#include <stdint.h>

#define B_ 2
#define T_ 1024
#define C_ 1024
#define H_ 16
#define D_ 64
#define NROW_ (B_*T_)     // 2048
#define M3_ (3*C_)        // 3072

// ---------------- device scratch (static, no allocation) ----------------
__device__ float g_qkv[NROW_ * M3_];     // 25.2 MB: [n][3C] qkv
__device__ float g_ylin[NROW_ * C_];     // 8.4 MB
__device__ float g_ysharp[NROW_ * C_];   // 8.4 MB

__device__ __forceinline__ float elup(float x) {
    return x > 0.f ? x + 1.f : __expf(x);
}

// ---------------- Kernel 1: QKV GEMM  (out = X @ W^T + b) ----------------
#define GBM 128
#define GBN 128
#define GBK 16

__global__ void __launch_bounds__(256) qkv_gemm_kernel(
    const float* __restrict__ X, const float* __restrict__ W, const float* __restrict__ bias)
{
    __shared__ float As[GBK][GBM + 1];
    __shared__ float Bs[GBK][GBN + 1];
    int tid = threadIdx.x;
    int tx = tid & 15, ty = tid >> 4;
    int n0 = blockIdx.y * GBM;
    int m0 = blockIdx.x * GBN;

    float acc[8][8];
#pragma unroll
    for (int i = 0; i < 8; i++)
#pragma unroll
        for (int j = 0; j < 8; j++) acc[i][j] = 0.f;

    for (int k0 = 0; k0 < C_; k0 += GBK) {
#pragma unroll
        for (int p = 0; p < 8; p++) {
            int l = tid + p * 256;
            int r = l >> 4, c = l & 15;
            As[c][r] = X[(n0 + r) * C_ + k0 + c];
            Bs[c][r] = W[(m0 + r) * C_ + k0 + c];
        }
        __syncthreads();
#pragma unroll
        for (int kk = 0; kk < GBK; kk++) {
            float a[8], b[8];
#pragma unroll
            for (int i = 0; i < 8; i++) a[i] = As[kk][ty + i * 16];
#pragma unroll
            for (int j = 0; j < 8; j++) b[j] = Bs[kk][tx + j * 16];
#pragma unroll
            for (int i = 0; i < 8; i++)
#pragma unroll
                for (int j = 0; j < 8; j++)
                    acc[i][j] = fmaf(a[i], b[j], acc[i][j]);
        }
        __syncthreads();
    }
#pragma unroll
    for (int i = 0; i < 8; i++) {
        int n = n0 + ty + i * 16;
#pragma unroll
        for (int j = 0; j < 8; j++) {
            int m = m0 + tx + j * 16;
            g_qkv[n * M3_ + m] = acc[i][j] + bias[m];
        }
    }
}

// ---------------- Kernel 2: causal softmax attention (flash-style) ----------------
// grid (qt=16, bh=32), 256 threads. Row i = tid>>2, lane4 = tid&3.
// P exchanged via shuffles within the 4-lane row group (no SMEM P buffer).
__global__ void __launch_bounds__(256) flash_kernel()
{
    extern __shared__ float sm[];
    float* Q = sm;                 // 64 x 65 (padded)
    float* K = Q + 64 * 65;        // 64 x 64 (float4-swizzled by j&3)
    float* V = K + 64 * 64;        // 64 x 64

    int qt = blockIdx.x, bh = blockIdx.y;
    int b = bh >> 4, h = bh & 15;
    int tid = threadIdx.x;
    int i = tid >> 2, lane4 = tid & 3;
    int lbase = (tid & 31) & ~3;   // lane id of lane4==0 in this row group
    int e0 = lane4 * 16;

    for (int l = tid; l < 64 * 64; l += 256) {
        int r = l >> 6, d = l & 63;
        Q[r * 65 + d] = g_qkv[(b * T_ + qt * 64 + r) * M3_ + h * 64 + d];
    }

    float acc[16];
#pragma unroll
    for (int e = 0; e < 16; e++) acc[e] = 0.f;
    float m_prev = -1e30f, l_sum = 0.f;

    for (int kt = 0; kt <= qt; kt++) {
        __syncthreads();
        for (int l = tid; l < 64 * 64; l += 256) {
            int r = l >> 6, d = l & 63;
            int gidx = (b * T_ + kt * 64 + r) * M3_ + h * 64 + d;
            int d4 = d >> 2;
            K[r * 64 + ((d4 ^ (r & 3)) << 2) + (d & 3)] = g_qkv[gidx + C_];
            V[r * 64 + d] = g_qkv[gidx + 2 * C_];
        }
        __syncthreads();

        // scores: this lane owns j = 4*jj + lane4
        float s[16];
#pragma unroll
        for (int jj = 0; jj < 16; jj++) s[jj] = 0.f;
        const float4* Kv = (const float4*)K;
#pragma unroll
        for (int d4 = 0; d4 < 16; d4++) {
            float q0 = Q[i * 65 + 4 * d4 + 0];
            float q1 = Q[i * 65 + 4 * d4 + 1];
            float q2 = Q[i * 65 + 4 * d4 + 2];
            float q3 = Q[i * 65 + 4 * d4 + 3];
#pragma unroll
            for (int jj = 0; jj < 16; jj++) {
                int j = 4 * jj + lane4;
                float4 kv = Kv[j * 16 + (d4 ^ lane4)];
                s[jj] += q0 * kv.x + q1 * kv.y + q2 * kv.z + q3 * kv.w;
            }
        }
        bool diag = (kt == qt);
        float mloc = -1e30f;
#pragma unroll
        for (int jj = 0; jj < 16; jj++) {
            int j = 4 * jj + lane4;
            float sv = s[jj] * 0.125f;
            if (diag && j > i) sv = -1e30f;
            s[jj] = sv;
            mloc = fmaxf(mloc, sv);
        }
        mloc = fmaxf(mloc, __shfl_xor_sync(0xffffffffu, mloc, 1));
        mloc = fmaxf(mloc, __shfl_xor_sync(0xffffffffu, mloc, 2));
        float m_new = fmaxf(m_prev, mloc);
        float corr = __expf(m_prev - m_new);
        float p[16];
        float psum = 0.f;
#pragma unroll
        for (int jj = 0; jj < 16; jj++) {
            p[jj] = __expf(s[jj] - m_new);
            psum += p[jj];
        }
        psum += __shfl_xor_sync(0xffffffffu, psum, 1);
        psum += __shfl_xor_sync(0xffffffffu, psum, 2);
        l_sum = l_sum * corr + psum;
        m_prev = m_new;
#pragma unroll
        for (int e = 0; e < 16; e++) acc[e] *= corr;

        // PV: j = 4*jj + l, p held by lane (lbase+l); broadcast via shfl
        const float4* Vv = (const float4*)V;
#pragma unroll
        for (int jj = 0; jj < 16; jj++) {
            float pj = p[jj];
#pragma unroll
            for (int l = 0; l < 4; l++) {
                float pb = __shfl_sync(0xffffffffu, pj, lbase + l);
                int j = 4 * jj + l;
#pragma unroll
                for (int e4 = 0; e4 < 4; e4++) {
                    float4 vv = Vv[j * 16 + lane4 * 4 + e4];
                    acc[e4 * 4 + 0] = fmaf(pb, vv.x, acc[e4 * 4 + 0]);
                    acc[e4 * 4 + 1] = fmaf(pb, vv.y, acc[e4 * 4 + 1]);
                    acc[e4 * 4 + 2] = fmaf(pb, vv.z, acc[e4 * 4 + 2]);
                    acc[e4 * 4 + 3] = fmaf(pb, vv.w, acc[e4 * 4 + 3]);
                }
            }
        }
    }
    float inv = 1.f / l_sum;
    int orow = (b * T_ + qt * 64 + i) * C_ + h * 64 + e0;
#pragma unroll
    for (int e = 0; e < 16; e++)
        g_ysharp[orow + e] = acc[e] * inv;
}

// ---------------- Kernel 3: linear attention, chunked state, e-split x2 ----------------
__global__ void __launch_bounds__(256) linear_kernel()
{
    extern __shared__ float sm[];
    float* QP   = sm;                  // 64 x 65
    float* KP   = QP + 64 * 65;        // 64 x 64 (swizzled)
    float* V    = KP + 64 * 64;        // 64 x 32 (this e half)
    float* P    = V + 64 * 32;         // 64 x 65
    float* S    = P + 64 * 65;         // 64 x 36 (state d x e-half, padded)
    float* ksum = S + 64 * 36;         // 64

    int bh = blockIdx.x >> 1, eh = blockIdx.x & 1;
    int b = bh >> 4, h = bh & 15;
    int tid = threadIdx.x;
    int i = tid >> 2, lane4 = tid & 3;
    int e0 = lane4 * 8;

    for (int l = tid; l < 64 * 36; l += 256) S[l] = 0.f;
    if (tid < 64) ksum[tid] = 0.f;

    for (int ch = 0; ch < 16; ch++) {
        __syncthreads();
        for (int l = tid; l < 64 * 64; l += 256) {
            int r = l >> 6, d = l & 63;
            int gidx = (b * T_ + ch * 64 + r) * M3_ + h * 64 + d;
            QP[r * 65 + d] = elup(g_qkv[gidx] * 0.125f);
            int d4 = d >> 2;
            KP[r * 64 + ((d4 ^ (r & 3)) << 2) + (d & 3)] = elup(g_qkv[gidx + C_] * 0.125f);
        }
        for (int l = tid; l < 64 * 32; l += 256) {
            int r = l >> 5, d = l & 31;
            V[l] = g_qkv[(b * T_ + ch * 64 + r) * M3_ + 2 * C_ + h * 64 + eh * 32 + d];
        }
        __syncthreads();

        float s[16];
#pragma unroll
        for (int jj = 0; jj < 16; jj++) s[jj] = 0.f;
        const float4* Kv = (const float4*)KP;
#pragma unroll
        for (int d4 = 0; d4 < 16; d4++) {
            float q0 = QP[i * 65 + 4 * d4 + 0];
            float q1 = QP[i * 65 + 4 * d4 + 1];
            float q2 = QP[i * 65 + 4 * d4 + 2];
            float q3 = QP[i * 65 + 4 * d4 + 3];
#pragma unroll
            for (int jj = 0; jj < 16; jj++) {
                int j = 4 * jj + lane4;
                float4 kv = Kv[j * 16 + (d4 ^ lane4)];
                s[jj] += q0 * kv.x + q1 * kv.y + q2 * kv.z + q3 * kv.w;
            }
        }
        float psum = 0.f;
#pragma unroll
        for (int jj = 0; jj < 16; jj++) {
            int j = 4 * jj + lane4;
            float sv = (j <= i) ? s[jj] : 0.f;
            P[i * 65 + j] = sv;
            psum += sv;
        }
        float dpart = 0.f;
#pragma unroll
        for (int dd = 0; dd < 16; dd++)
            dpart += QP[i * 65 + lane4 * 16 + dd] * ksum[lane4 * 16 + dd];
        float den = psum + dpart;
        den += __shfl_xor_sync(0xffffffffu, den, 1);
        den += __shfl_xor_sync(0xffffffffu, den, 2);
        den += 1e-4f;

        float num[8];
#pragma unroll
        for (int e = 0; e < 8; e++) num[e] = 0.f;
        const float4* Sv = (const float4*)S;
#pragma unroll 8
        for (int d = 0; d < 64; d++) {
            float q = QP[i * 65 + d];
            float4 s0 = Sv[d * 9 + lane4 * 2 + 0];
            float4 s1 = Sv[d * 9 + lane4 * 2 + 1];
            num[0] = fmaf(q, s0.x, num[0]); num[1] = fmaf(q, s0.y, num[1]);
            num[2] = fmaf(q, s0.z, num[2]); num[3] = fmaf(q, s0.w, num[3]);
            num[4] = fmaf(q, s1.x, num[4]); num[5] = fmaf(q, s1.y, num[5]);
            num[6] = fmaf(q, s1.z, num[6]); num[7] = fmaf(q, s1.w, num[7]);
        }
        __syncwarp();
        const float4* Vv = (const float4*)V;
#pragma unroll 8
        for (int j = 0; j < 64; j++) {
            float pv = P[i * 65 + j];
            float4 v0 = Vv[j * 8 + lane4 * 2 + 0];
            float4 v1 = Vv[j * 8 + lane4 * 2 + 1];
            num[0] = fmaf(pv, v0.x, num[0]); num[1] = fmaf(pv, v0.y, num[1]);
            num[2] = fmaf(pv, v0.z, num[2]); num[3] = fmaf(pv, v0.w, num[3]);
            num[4] = fmaf(pv, v1.x, num[4]); num[5] = fmaf(pv, v1.y, num[5]);
            num[6] = fmaf(pv, v1.z, num[6]); num[7] = fmaf(pv, v1.w, num[7]);
        }
        float invd = 1.f / den;
        int orow = (b * T_ + ch * 64 + i) * C_ + h * 64 + eh * 32 + e0;
#pragma unroll
        for (int e = 0; e < 8; e++)
            g_ylin[orow + e] = num[e] * invd;

        __syncthreads();  // all state reads done before update

        {
            int d = i;
            int d4 = d >> 2, dm = d & 3;
            float a2[8];
#pragma unroll
            for (int e = 0; e < 8; e++) a2[e] = 0.f;
            float ks_add = 0.f;
#pragma unroll 8
            for (int j = 0; j < 64; j++) {
                float kp = KP[j * 64 + ((d4 ^ (j & 3)) << 2) + dm];
                float4 v0 = Vv[j * 8 + lane4 * 2 + 0];
                float4 v1 = Vv[j * 8 + lane4 * 2 + 1];
                a2[0] = fmaf(kp, v0.x, a2[0]); a2[1] = fmaf(kp, v0.y, a2[1]);
                a2[2] = fmaf(kp, v0.z, a2[2]); a2[3] = fmaf(kp, v0.w, a2[3]);
                a2[4] = fmaf(kp, v1.x, a2[4]); a2[5] = fmaf(kp, v1.y, a2[5]);
                a2[6] = fmaf(kp, v1.z, a2[6]); a2[7] = fmaf(kp, v1.w, a2[7]);
                ks_add += kp;
            }
#pragma unroll
            for (int e = 0; e < 8; e++)
                S[d * 36 + e0 + e] += a2[e];
            if (lane4 == 0) ksum[d] += ks_add;
        }
    }
}

// ---------------- Kernel 4: combine + LNs + block mix + grid proj ----------------
__device__ __forceinline__ void block_ln_stats(float lsum, float lsq, float* red,
                                               float* mean, float* rstd)
{
#pragma unroll
    for (int m = 16; m >= 1; m >>= 1) {
        lsum += __shfl_xor_sync(0xffffffffu, lsum, m);
        lsq  += __shfl_xor_sync(0xffffffffu, lsq, m);
    }
    int w = threadIdx.x >> 5;
    if ((threadIdx.x & 31) == 0) { red[w] = lsum; red[8 + w] = lsq; }
    __syncthreads();
    if (threadIdx.x == 0) {
        float s = 0.f, q = 0.f;
#pragma unroll
        for (int k = 0; k < 8; k++) { s += red[k]; q += red[8 + k]; }
        float mu = s * (1.f / 1024.f);
        red[16] = mu;
        red[17] = rsqrtf(q * (1.f / 1024.f) - mu * mu + 1e-5f);
    }
    __syncthreads();
    *mean = red[16];
    *rstd = red[17];
}

__global__ void __launch_bounds__(256) combine_kernel(
    const float* __restrict__ fg,
    const float* __restrict__ attn_g, const float* __restrict__ attn_b,
    const float* __restrict__ out_g,  const float* __restrict__ out_b,
    const float* __restrict__ pre_g,  const float* __restrict__ pre_b,
    const float* __restrict__ bw,     const float* __restrict__ wrow,
    const float* __restrict__ wcol,   const float* __restrict__ palpha,
    const float* __restrict__ pbias,  float* __restrict__ out)
{
    __shared__ float sx[1024];
    __shared__ float sy[1024];
    __shared__ float sz[1024];
    __shared__ float red[32];

    int n = blockIdx.x, tid = threadIdx.x;
    int c0 = tid * 4;
    float afg = 1.f / (1.f + __expf(-fg[0]));

    float yl[4], ys[4], yv[4];
    float hsum = 0.f, hsq = 0.f;
#pragma unroll
    for (int k = 0; k < 4; k++) {
        yl[k] = g_ylin[n * C_ + c0 + k];
        ys[k] = g_ysharp[n * C_ + c0 + k];
        hsum += yl[k];
        hsq  += yl[k] * yl[k];
    }
#pragma unroll
    for (int m = 1; m < 16; m <<= 1) {
        hsum += __shfl_xor_sync(0xffffffffu, hsum, m);
        hsq  += __shfl_xor_sync(0xffffffffu, hsq, m);
    }
    float hmean = hsum * (1.f / 64.f);
    float hrstd = rsqrtf(hsq * (1.f / 64.f) - hmean * hmean + 1e-5f);
#pragma unroll
    for (int k = 0; k < 4; k++) {
        int d = (c0 + k) & 63;
        float v = (yl[k] - hmean) * hrstd * attn_g[d] + attn_b[d];
        yv[k] = afg * ys[k] + (1.f - afg) * v;
    }

    float lsum = 0.f, lsq = 0.f;
#pragma unroll
    for (int k = 0; k < 4; k++) { lsum += yv[k]; lsq += yv[k] * yv[k]; }
    float mu, rs;
    block_ln_stats(lsum, lsq, red, &mu, &rs);
#pragma unroll
    for (int k = 0; k < 4; k++)
        yv[k] = (yv[k] - mu) * rs * out_g[c0 + k] + out_b[c0 + k];

    lsum = 0.f; lsq = 0.f;
#pragma unroll
    for (int k = 0; k < 4; k++) { lsum += yv[k]; lsq += yv[k] * yv[k]; }
    block_ln_stats(lsum, lsq, red, &mu, &rs);
#pragma unroll
    for (int k = 0; k < 4; k++)
        sx[c0 + k] = (yv[k] - mu) * rs * pre_g[c0 + k] + pre_b[c0 + k];
    __syncthreads();

    float ym[4], zv[4];
#pragma unroll
    for (int k = 0; k < 4; k++) {
        int c = c0 + k;
        int g = c >> 4, j = c & 15;
        float a = 0.f;
#pragma unroll
        for (int ii = 0; ii < 16; ii++)
            a = fmaf(sx[g * 16 + ii], bw[g * 256 + ii * 16 + j], a);
        ym[k] = a;

        int gi = c >> 5, cc = c & 31;
        float z = 0.f;
#pragma unroll
        for (int jj = 0; jj < 32; jj++)
            z = fmaf(sx[gi * 32 + jj], wcol[jj * 32 + cc], z);
        zv[k] = z;
    }
#pragma unroll
    for (int k = 0; k < 4; k++) { sy[c0 + k] = ym[k]; sz[c0 + k] = zv[k]; }
    __syncthreads();

    float pa = palpha[0];
#pragma unroll
    for (int k = 0; k < 4; k++) {
        int c = c0 + k;
        int gi = c >> 5, r = c & 31;
        float zz = 0.f;
#pragma unroll
        for (int cc = 0; cc < 32; cc++)
            zz = fmaf(sz[gi * 32 + cc], wrow[r * 32 + cc], zz);
        out[n * C_ + c] = sy[1023 - c] + pa * zz + pbias[c];
    }
}

// ---------------- launch ----------------
extern "C" void kernel_launch(void* const* d_in, const int* in_sizes, int n_in,
                              void* d_out, int out_size)
{
    const float* x      = (const float*)d_in[0];
    const float* w      = (const float*)d_in[1];
    const float* cb     = (const float*)d_in[2];
    const float* fg     = (const float*)d_in[3];
    const float* ag     = (const float*)d_in[4];
    const float* ab     = (const float*)d_in[5];
    const float* og     = (const float*)d_in[6];
    const float* ob     = (const float*)d_in[7];
    const float* pg     = (const float*)d_in[8];
    const float* pb     = (const float*)d_in[9];
    const float* bw     = (const float*)d_in[10];
    const float* wrow   = (const float*)d_in[11];
    const float* wcol   = (const float*)d_in[12];
    const float* palpha = (const float*)d_in[13];
    const float* pbias  = (const float*)d_in[14];
    float* out = (float*)d_out;

    const int FLASH_SMEM = (64 * 65 + 64 * 64 + 64 * 64) * 4;                          // 49408
    const int LIN_SMEM   = (64 * 65 + 64 * 64 + 64 * 32 + 64 * 65 + 64 * 36 + 64) * 4; // 67328
    cudaFuncSetAttribute(flash_kernel, cudaFuncAttributeMaxDynamicSharedMemorySize, FLASH_SMEM);
    cudaFuncSetAttribute(linear_kernel, cudaFuncAttributeMaxDynamicSharedMemorySize, LIN_SMEM);

    dim3 gemm_grid(M3_ / GBN, NROW_ / GBM);  // 24 x 16
    qkv_gemm_kernel<<<gemm_grid, 256>>>(x, w, cb);
    flash_kernel<<<dim3(T_ / 64, B_ * H_), 256, FLASH_SMEM>>>();
    linear_kernel<<<B_ * H_ * 2, 256, LIN_SMEM>>>();
    combine_kernel<<<NROW_, 256>>>(fg, ag, ab, og, ob, pg, pb, bw, wrow, wcol,
                                   palpha, pbias, out);
}

// round 11
// speedup vs baseline: 1.2739x; 1.2739x over previous
#include <cuda_runtime.h>
#include <cuda_bf16.h>
#include <math.h>
#include <stdint.h>

#define B_ 2
#define T_ 1024
#define C_ 1024
#define H_ 16
#define D_ 64
#define NROW_ (B_*T_)     // 2048
#define M3_ (3*C_)        // 3072

// ---------------- device scratch (static, no allocation) ----------------
__device__ float g_qkv[NROW_ * M3_];            // 25.2 MB
__device__ float g_ylin[NROW_ * C_];            // 8.4 MB
__device__ float g_ysharp[NROW_ * C_];          // 8.4 MB
__device__ __nv_bfloat16 g_xhi[NROW_ * C_];     // 4.2 MB
__device__ __nv_bfloat16 g_xlo[NROW_ * C_];     // 4.2 MB
__device__ __nv_bfloat16 g_whi[M3_ * C_];       // 6.3 MB
__device__ __nv_bfloat16 g_wlo[M3_ * C_];       // 6.3 MB

__device__ __forceinline__ float elup(float x) {
    return x > 0.f ? x + 1.f : __expf(x);
}

__device__ __forceinline__ uint32_t smem_u32(const void* p) {
    uint32_t a;
    asm("{ .reg .u64 t; cvta.to.shared.u64 t, %1; cvt.u32.u64 %0, t; }" : "=r"(a) : "l"(p));
    return a;
}
__device__ __forceinline__ void ldm_x4(uint32_t a[4], uint32_t addr) {
    asm volatile("ldmatrix.sync.aligned.m8n8.x4.shared.b16 {%0,%1,%2,%3}, [%4];"
                 : "=r"(a[0]), "=r"(a[1]), "=r"(a[2]), "=r"(a[3]) : "r"(addr));
}
__device__ __forceinline__ void ldm_x2(uint32_t a[2], uint32_t addr) {
    asm volatile("ldmatrix.sync.aligned.m8n8.x2.shared.b16 {%0,%1}, [%2];"
                 : "=r"(a[0]), "=r"(a[1]) : "r"(addr));
}
__device__ __forceinline__ void mma16816(float c[4], const uint32_t a[4], const uint32_t b[2]) {
    asm volatile("mma.sync.aligned.m16n8k16.row.col.f32.bf16.bf16.f32 "
                 "{%0,%1,%2,%3}, {%4,%5,%6,%7}, {%8,%9}, {%0,%1,%2,%3};"
                 : "+f"(c[0]), "+f"(c[1]), "+f"(c[2]), "+f"(c[3])
                 : "r"(a[0]), "r"(a[1]), "r"(a[2]), "r"(a[3]), "r"(b[0]), "r"(b[1]));
}

// ---------------- Kernel 0: hi/lo bf16 split (float4 streaming) ----------------
__global__ void __launch_bounds__(256) split_kernel(const float* __restrict__ X,
                                                    const float* __restrict__ W)
{
    int nx4 = NROW_ * C_ / 4;       // 524288
    int nw4 = M3_ * C_ / 4;         // 786432
    int tot = nx4 + nw4;
    for (int idx = blockIdx.x * 256 + threadIdx.x; idx < tot; idx += gridDim.x * 256) {
        const float4 v = (idx < nx4) ? ((const float4*)X)[idx]
                                     : ((const float4*)W)[idx - nx4];
        float e[4] = {v.x, v.y, v.z, v.w};
        __nv_bfloat16 hi[4], lo[4];
#pragma unroll
        for (int k = 0; k < 4; k++) {
            hi[k] = __float2bfloat16(e[k]);
            lo[k] = __float2bfloat16(e[k] - __bfloat162float(hi[k]));
        }
        if (idx < nx4) {
            ((uint2*)g_xhi)[idx] = *(uint2*)hi;
            ((uint2*)g_xlo)[idx] = *(uint2*)lo;
        } else {
            ((uint2*)g_whi)[idx - nx4] = *(uint2*)hi;
            ((uint2*)g_wlo)[idx - nx4] = *(uint2*)lo;
        }
    }
}

// ---------------- Kernel 1: QKV GEMM via mma.sync bf16 hi/lo ----------------
// out[n][m] = X[n]·W[m] + b[m].  128x128 tile, kc=32, warps 2(M)x4(N), 64x32/warp.
// SMEM rows: 32 bf16 data padded to 40 bf16 (80B) -> ldmatrix conflict-free.
#define ROWB 80

__global__ void __launch_bounds__(256) qkv_mma_kernel(const float* __restrict__ bias)
{
    __shared__ __align__(16) char sXhi[128 * ROWB];
    __shared__ __align__(16) char sXlo[128 * ROWB];
    __shared__ __align__(16) char sWhi[128 * ROWB];
    __shared__ __align__(16) char sWlo[128 * ROWB];

    int tid = threadIdx.x;
    int wid = tid >> 5, lane = tid & 31;
    int wm = wid >> 2, wn = wid & 3;
    int n0 = blockIdx.y * 128;
    int m0 = blockIdx.x * 128;

    uint32_t bXhi = smem_u32(sXhi), bXlo = smem_u32(sXlo);
    uint32_t bWhi = smem_u32(sWhi), bWlo = smem_u32(sWlo);

    float acc[4][4][4];
#pragma unroll
    for (int mt = 0; mt < 4; mt++)
#pragma unroll
        for (int nt = 0; nt < 4; nt++)
#pragma unroll
            for (int k = 0; k < 4; k++) acc[mt][nt][k] = 0.f;

    int a_mat = lane >> 3, a_row = lane & 7;
    int a_roff = ((a_mat & 1) << 3) + a_row;
    int a_uoff = a_mat >> 1;
    int b_row = lane & 7;
    int b_uoff = (lane >> 3) & 1;

    for (int kc = 0; kc < 32; kc++) {
#pragma unroll
        for (int it = 0; it < 2; it++) {
            int l = tid + it * 256;
            int r = l >> 2, u = l & 3;
            uint32_t off = r * ROWB + u * 16;
            int gx = (n0 + r) * C_ + kc * 32 + u * 8;
            int gw = (m0 + r) * C_ + kc * 32 + u * 8;
            *(uint4*)(sXhi + off) = *(const uint4*)(g_xhi + gx);
            *(uint4*)(sXlo + off) = *(const uint4*)(g_xlo + gx);
            *(uint4*)(sWhi + off) = *(const uint4*)(g_whi + gw);
            *(uint4*)(sWlo + off) = *(const uint4*)(g_wlo + gw);
        }
        __syncthreads();

#pragma unroll
        for (int ks = 0; ks < 2; ks++) {
            uint32_t ahi[4][4], alo[4][4];
#pragma unroll
            for (int mt = 0; mt < 4; mt++) {
                int r = wm * 64 + mt * 16 + a_roff;
                uint32_t off = r * ROWB + (ks * 2 + a_uoff) * 16;
                ldm_x4(ahi[mt], bXhi + off);
                ldm_x4(alo[mt], bXlo + off);
            }
            uint32_t bhi[4][2], blo[4][2];
#pragma unroll
            for (int nt = 0; nt < 4; nt++) {
                int r = wn * 32 + nt * 8 + b_row;
                uint32_t off = r * ROWB + (ks * 2 + b_uoff) * 16;
                ldm_x2(bhi[nt], bWhi + off);
                ldm_x2(blo[nt], bWlo + off);
            }
#pragma unroll
            for (int mt = 0; mt < 4; mt++)
#pragma unroll
                for (int nt = 0; nt < 4; nt++) {
                    mma16816(acc[mt][nt], ahi[mt], bhi[nt]);
                    mma16816(acc[mt][nt], ahi[mt], blo[nt]);
                    mma16816(acc[mt][nt], alo[mt], bhi[nt]);
                }
        }
        __syncthreads();
    }

    int g = lane >> 2, tg = lane & 3;
#pragma unroll
    for (int mt = 0; mt < 4; mt++) {
        int r0 = n0 + wm * 64 + mt * 16 + g;
#pragma unroll
        for (int nt = 0; nt < 4; nt++) {
            int c = m0 + wn * 32 + nt * 8 + tg * 2;
            float b0 = bias[c], b1 = bias[c + 1];
            *(float2*)(g_qkv + r0 * M3_ + c) =
                make_float2(acc[mt][nt][0] + b0, acc[mt][nt][1] + b1);
            *(float2*)(g_qkv + (r0 + 8) * M3_ + c) =
                make_float2(acc[mt][nt][2] + b0, acc[mt][nt][3] + b1);
        }
    }
}

// ---------------- Kernel 2: causal softmax attention (flash-style) ----------------
__global__ void __launch_bounds__(256) flash_kernel()
{
    extern __shared__ float sm[];
    float* Q = sm;                 // 64 x 65
    float* K = Q + 64 * 65;        // 64 x 64 (float4-swizzled)
    float* V = K + 64 * 64;        // 64 x 64

    int qt = blockIdx.x, bh = blockIdx.y;
    int b = bh >> 4, h = bh & 15;
    int tid = threadIdx.x;
    int i = tid >> 2, lane4 = tid & 3;
    int lbase = (tid & 31) & ~3;
    int e0 = lane4 * 16;

    for (int l = tid; l < 64 * 64; l += 256) {
        int r = l >> 6, d = l & 63;
        Q[r * 65 + d] = g_qkv[(b * T_ + qt * 64 + r) * M3_ + h * 64 + d];
    }

    float acc[16];
#pragma unroll
    for (int e = 0; e < 16; e++) acc[e] = 0.f;
    float m_prev = -1e30f, l_sum = 0.f;

    for (int kt = 0; kt <= qt; kt++) {
        __syncthreads();
        for (int l = tid; l < 64 * 64; l += 256) {
            int r = l >> 6, d = l & 63;
            int gidx = (b * T_ + kt * 64 + r) * M3_ + h * 64 + d;
            int d4 = d >> 2;
            K[r * 64 + ((d4 ^ (r & 3)) << 2) + (d & 3)] = g_qkv[gidx + C_];
            V[r * 64 + d] = g_qkv[gidx + 2 * C_];
        }
        __syncthreads();

        float s[16];
#pragma unroll
        for (int jj = 0; jj < 16; jj++) s[jj] = 0.f;
        const float4* Kv = (const float4*)K;
#pragma unroll
        for (int d4 = 0; d4 < 16; d4++) {
            float q0 = Q[i * 65 + 4 * d4 + 0];
            float q1 = Q[i * 65 + 4 * d4 + 1];
            float q2 = Q[i * 65 + 4 * d4 + 2];
            float q3 = Q[i * 65 + 4 * d4 + 3];
#pragma unroll
            for (int jj = 0; jj < 16; jj++) {
                int j = 4 * jj + lane4;
                float4 kv = Kv[j * 16 + (d4 ^ lane4)];
                s[jj] += q0 * kv.x + q1 * kv.y + q2 * kv.z + q3 * kv.w;
            }
        }
        bool diag = (kt == qt);
        float mloc = -1e30f;
#pragma unroll
        for (int jj = 0; jj < 16; jj++) {
            int j = 4 * jj + lane4;
            float sv = s[jj] * 0.125f;
            if (diag && j > i) sv = -1e30f;
            s[jj] = sv;
            mloc = fmaxf(mloc, sv);
        }
        mloc = fmaxf(mloc, __shfl_xor_sync(0xffffffffu, mloc, 1));
        mloc = fmaxf(mloc, __shfl_xor_sync(0xffffffffu, mloc, 2));
        float m_new = fmaxf(m_prev, mloc);
        float corr = __expf(m_prev - m_new);
        float p[16];
        float psum = 0.f;
#pragma unroll
        for (int jj = 0; jj < 16; jj++) {
            p[jj] = __expf(s[jj] - m_new);
            psum += p[jj];
        }
        psum += __shfl_xor_sync(0xffffffffu, psum, 1);
        psum += __shfl_xor_sync(0xffffffffu, psum, 2);
        l_sum = l_sum * corr + psum;
        m_prev = m_new;
#pragma unroll
        for (int e = 0; e < 16; e++) acc[e] *= corr;

        const float4* Vv = (const float4*)V;
#pragma unroll
        for (int jj = 0; jj < 16; jj++) {
            float pj = p[jj];
#pragma unroll
            for (int l = 0; l < 4; l++) {
                float pb = __shfl_sync(0xffffffffu, pj, lbase + l);
                int j = 4 * jj + l;
#pragma unroll
                for (int e4 = 0; e4 < 4; e4++) {
                    float4 vv = Vv[j * 16 + lane4 * 4 + e4];
                    acc[e4 * 4 + 0] = fmaf(pb, vv.x, acc[e4 * 4 + 0]);
                    acc[e4 * 4 + 1] = fmaf(pb, vv.y, acc[e4 * 4 + 1]);
                    acc[e4 * 4 + 2] = fmaf(pb, vv.z, acc[e4 * 4 + 2]);
                    acc[e4 * 4 + 3] = fmaf(pb, vv.w, acc[e4 * 4 + 3]);
                }
            }
        }
    }
    float inv = 1.f / l_sum;
    int orow = (b * T_ + qt * 64 + i) * C_ + h * 64 + e0;
#pragma unroll
    for (int e = 0; e < 16; e++)
        g_ysharp[orow + e] = acc[e] * inv;
}

// ---------------- Kernel 3: linear attention, chunked state, e-split x2 ----------------
__global__ void __launch_bounds__(256) linear_kernel()
{
    extern __shared__ float sm[];
    float* QP   = sm;                  // 64 x 65
    float* KP   = QP + 64 * 65;        // 64 x 64 (swizzled)
    float* V    = KP + 64 * 64;        // 64 x 32
    float* P    = V + 64 * 32;         // 64 x 65
    float* S    = P + 64 * 65;         // 64 x 36
    float* ksum = S + 64 * 36;         // 64

    int bh = blockIdx.x >> 1, eh = blockIdx.x & 1;
    int b = bh >> 4, h = bh & 15;
    int tid = threadIdx.x;
    int i = tid >> 2, lane4 = tid & 3;
    int e0 = lane4 * 8;

    for (int l = tid; l < 64 * 36; l += 256) S[l] = 0.f;
    if (tid < 64) ksum[tid] = 0.f;

    for (int ch = 0; ch < 16; ch++) {
        __syncthreads();
        for (int l = tid; l < 64 * 64; l += 256) {
            int r = l >> 6, d = l & 63;
            int gidx = (b * T_ + ch * 64 + r) * M3_ + h * 64 + d;
            QP[r * 65 + d] = elup(g_qkv[gidx] * 0.125f);
            int d4 = d >> 2;
            KP[r * 64 + ((d4 ^ (r & 3)) << 2) + (d & 3)] = elup(g_qkv[gidx + C_] * 0.125f);
        }
        for (int l = tid; l < 64 * 32; l += 256) {
            int r = l >> 5, d = l & 31;
            V[l] = g_qkv[(b * T_ + ch * 64 + r) * M3_ + 2 * C_ + h * 64 + eh * 32 + d];
        }
        __syncthreads();

        float s[16];
#pragma unroll
        for (int jj = 0; jj < 16; jj++) s[jj] = 0.f;
        const float4* Kv = (const float4*)KP;
#pragma unroll
        for (int d4 = 0; d4 < 16; d4++) {
            float q0 = QP[i * 65 + 4 * d4 + 0];
            float q1 = QP[i * 65 + 4 * d4 + 1];
            float q2 = QP[i * 65 + 4 * d4 + 2];
            float q3 = QP[i * 65 + 4 * d4 + 3];
#pragma unroll
            for (int jj = 0; jj < 16; jj++) {
                int j = 4 * jj + lane4;
                float4 kv = Kv[j * 16 + (d4 ^ lane4)];
                s[jj] += q0 * kv.x + q1 * kv.y + q2 * kv.z + q3 * kv.w;
            }
        }
        float psum = 0.f;
#pragma unroll
        for (int jj = 0; jj < 16; jj++) {
            int j = 4 * jj + lane4;
            float sv = (j <= i) ? s[jj] : 0.f;
            P[i * 65 + j] = sv;
            psum += sv;
        }
        float dpart = 0.f;
#pragma unroll
        for (int dd = 0; dd < 16; dd++)
            dpart += QP[i * 65 + lane4 * 16 + dd] * ksum[lane4 * 16 + dd];
        float den = psum + dpart;
        den += __shfl_xor_sync(0xffffffffu, den, 1);
        den += __shfl_xor_sync(0xffffffffu, den, 2);
        den += 1e-4f;

        float num[8];
#pragma unroll
        for (int e = 0; e < 8; e++) num[e] = 0.f;
        const float4* Sv = (const float4*)S;
#pragma unroll 8
        for (int d = 0; d < 64; d++) {
            float q = QP[i * 65 + d];
            float4 s0 = Sv[d * 9 + lane4 * 2 + 0];
            float4 s1 = Sv[d * 9 + lane4 * 2 + 1];
            num[0] = fmaf(q, s0.x, num[0]); num[1] = fmaf(q, s0.y, num[1]);
            num[2] = fmaf(q, s0.z, num[2]); num[3] = fmaf(q, s0.w, num[3]);
            num[4] = fmaf(q, s1.x, num[4]); num[5] = fmaf(q, s1.y, num[5]);
            num[6] = fmaf(q, s1.z, num[6]); num[7] = fmaf(q, s1.w, num[7]);
        }
        __syncwarp();
        const float4* Vv = (const float4*)V;
#pragma unroll 8
        for (int j = 0; j < 64; j++) {
            float pv = P[i * 65 + j];
            float4 v0 = Vv[j * 8 + lane4 * 2 + 0];
            float4 v1 = Vv[j * 8 + lane4 * 2 + 1];
            num[0] = fmaf(pv, v0.x, num[0]); num[1] = fmaf(pv, v0.y, num[1]);
            num[2] = fmaf(pv, v0.z, num[2]); num[3] = fmaf(pv, v0.w, num[3]);
            num[4] = fmaf(pv, v1.x, num[4]); num[5] = fmaf(pv, v1.y, num[5]);
            num[6] = fmaf(pv, v1.z, num[6]); num[7] = fmaf(pv, v1.w, num[7]);
        }
        float invd = 1.f / den;
        int orow = (b * T_ + ch * 64 + i) * C_ + h * 64 + eh * 32 + e0;
#pragma unroll
        for (int e = 0; e < 8; e++)
            g_ylin[orow + e] = num[e] * invd;

        __syncthreads();

        {
            int d = i;
            int d4 = d >> 2, dm = d & 3;
            float a2[8];
#pragma unroll
            for (int e = 0; e < 8; e++) a2[e] = 0.f;
            float ks_add = 0.f;
#pragma unroll 8
            for (int j = 0; j < 64; j++) {
                float kp = KP[j * 64 + ((d4 ^ (j & 3)) << 2) + dm];
                float4 v0 = Vv[j * 8 + lane4 * 2 + 0];
                float4 v1 = Vv[j * 8 + lane4 * 2 + 1];
                a2[0] = fmaf(kp, v0.x, a2[0]); a2[1] = fmaf(kp, v0.y, a2[1]);
                a2[2] = fmaf(kp, v0.z, a2[2]); a2[3] = fmaf(kp, v0.w, a2[3]);
                a2[4] = fmaf(kp, v1.x, a2[4]); a2[5] = fmaf(kp, v1.y, a2[5]);
                a2[6] = fmaf(kp, v1.z, a2[6]); a2[7] = fmaf(kp, v1.w, a2[7]);
                ks_add += kp;
            }
#pragma unroll
            for (int e = 0; e < 8; e++)
                S[d * 36 + e0 + e] += a2[e];
            if (lane4 == 0) ksum[d] += ks_add;
        }
    }
}

// ---------------- Kernel 4: combine (vectorized float4) ----------------
__device__ __forceinline__ void block_ln_stats(float lsum, float lsq, float* red,
                                               float* mean, float* rstd)
{
#pragma unroll
    for (int m = 16; m >= 1; m >>= 1) {
        lsum += __shfl_xor_sync(0xffffffffu, lsum, m);
        lsq  += __shfl_xor_sync(0xffffffffu, lsq, m);
    }
    int w = threadIdx.x >> 5;
    if ((threadIdx.x & 31) == 0) { red[w] = lsum; red[8 + w] = lsq; }
    __syncthreads();
    if (threadIdx.x == 0) {
        float s = 0.f, q = 0.f;
#pragma unroll
        for (int k = 0; k < 8; k++) { s += red[k]; q += red[8 + k]; }
        float mu = s * (1.f / 1024.f);
        red[16] = mu;
        red[17] = rsqrtf(q * (1.f / 1024.f) - mu * mu + 1e-5f);
    }
    __syncthreads();
    *mean = red[16];
    *rstd = red[17];
}

__global__ void __launch_bounds__(256) combine_kernel(
    const float* __restrict__ fg,
    const float* __restrict__ attn_g, const float* __restrict__ attn_b,
    const float* __restrict__ out_g,  const float* __restrict__ out_b,
    const float* __restrict__ pre_g,  const float* __restrict__ pre_b,
    const float* __restrict__ bw,     const float* __restrict__ wrow,
    const float* __restrict__ wcol,   const float* __restrict__ palpha,
    const float* __restrict__ pbias,  float* __restrict__ out)
{
    __shared__ float sx[1024];
    __shared__ float sy[1024];
    __shared__ float sz[1024];
    __shared__ float red[32];

    int n = blockIdx.x, tid = threadIdx.x;
    int c0 = tid * 4;
    float afg = 1.f / (1.f + __expf(-fg[0]));

    float4 ylv = *(const float4*)(g_ylin + n * C_ + c0);
    float4 ysv = *(const float4*)(g_ysharp + n * C_ + c0);
    float yl[4] = {ylv.x, ylv.y, ylv.z, ylv.w};
    float ys[4] = {ysv.x, ysv.y, ysv.z, ysv.w};
    float yv[4];
    float hsum = 0.f, hsq = 0.f;
#pragma unroll
    for (int k = 0; k < 4; k++) { hsum += yl[k]; hsq += yl[k] * yl[k]; }
#pragma unroll
    for (int m = 1; m < 16; m <<= 1) {
        hsum += __shfl_xor_sync(0xffffffffu, hsum, m);
        hsq  += __shfl_xor_sync(0xffffffffu, hsq, m);
    }
    float hmean = hsum * (1.f / 64.f);
    float hrstd = rsqrtf(hsq * (1.f / 64.f) - hmean * hmean + 1e-5f);
#pragma unroll
    for (int k = 0; k < 4; k++) {
        int d = (c0 + k) & 63;
        float v = (yl[k] - hmean) * hrstd * attn_g[d] + attn_b[d];
        yv[k] = afg * ys[k] + (1.f - afg) * v;
    }

    float lsum = 0.f, lsq = 0.f;
#pragma unroll
    for (int k = 0; k < 4; k++) { lsum += yv[k]; lsq += yv[k] * yv[k]; }
    float mu, rs;
    block_ln_stats(lsum, lsq, red, &mu, &rs);
#pragma unroll
    for (int k = 0; k < 4; k++)
        yv[k] = (yv[k] - mu) * rs * out_g[c0 + k] + out_b[c0 + k];

    lsum = 0.f; lsq = 0.f;
#pragma unroll
    for (int k = 0; k < 4; k++) { lsum += yv[k]; lsq += yv[k] * yv[k]; }
    block_ln_stats(lsum, lsq, red, &mu, &rs);
#pragma unroll
    for (int k = 0; k < 4; k++)
        sx[c0 + k] = (yv[k] - mu) * rs * pre_g[c0 + k] + pre_b[c0 + k];
    __syncthreads();

    const float4* sx4 = (const float4*)sx;

    int g = c0 >> 4, j0 = c0 & 15;
    float4 ymv = make_float4(0.f, 0.f, 0.f, 0.f);
#pragma unroll
    for (int ii4 = 0; ii4 < 4; ii4++) {
        float4 sxv = sx4[g * 4 + ii4];
        float sxe[4] = {sxv.x, sxv.y, sxv.z, sxv.w};
#pragma unroll
        for (int t = 0; t < 4; t++) {
            int ii = ii4 * 4 + t;
            float4 bwv = *(const float4*)(bw + g * 256 + ii * 16 + j0);
            ymv.x = fmaf(sxe[t], bwv.x, ymv.x);
            ymv.y = fmaf(sxe[t], bwv.y, ymv.y);
            ymv.z = fmaf(sxe[t], bwv.z, ymv.z);
            ymv.w = fmaf(sxe[t], bwv.w, ymv.w);
        }
    }

    int gi = c0 >> 5, cc0 = c0 & 31;
    float4 zvv = make_float4(0.f, 0.f, 0.f, 0.f);
#pragma unroll
    for (int jj4 = 0; jj4 < 8; jj4++) {
        float4 sxv = sx4[gi * 8 + jj4];
        float sxe[4] = {sxv.x, sxv.y, sxv.z, sxv.w};
#pragma unroll
        for (int t = 0; t < 4; t++) {
            int jj = jj4 * 4 + t;
            float4 wcv = *(const float4*)(wcol + jj * 32 + cc0);
            zvv.x = fmaf(sxe[t], wcv.x, zvv.x);
            zvv.y = fmaf(sxe[t], wcv.y, zvv.y);
            zvv.z = fmaf(sxe[t], wcv.z, zvv.z);
            zvv.w = fmaf(sxe[t], wcv.w, zvv.w);
        }
    }
    *(float4*)(sy + c0) = ymv;
    *(float4*)(sz + c0) = zvv;
    __syncthreads();

    const float4* sz4 = (const float4*)sz;
    int r0 = c0 & 31;
    float zz[4] = {0.f, 0.f, 0.f, 0.f};
#pragma unroll
    for (int cc4 = 0; cc4 < 8; cc4++) {
        float4 szv = sz4[gi * 8 + cc4];
#pragma unroll
        for (int k = 0; k < 4; k++) {
            float4 wrv = *(const float4*)(wrow + (r0 + k) * 32 + cc4 * 4);
            zz[k] += szv.x * wrv.x + szv.y * wrv.y + szv.z * wrv.z + szv.w * wrv.w;
        }
    }

    float pa = palpha[0];
    float4 pbv = *(const float4*)(pbias + c0);
    float pbe[4] = {pbv.x, pbv.y, pbv.z, pbv.w};
#pragma unroll
    for (int k = 0; k < 4; k++) {
        int c = c0 + k;
        out[n * C_ + c] = sy[1023 - c] + pa * zz[k] + pbe[k];
    }
}

// ---------------- launch ----------------
extern "C" void kernel_launch(void* const* d_in, const int* in_sizes, int n_in,
                              void* d_out, int out_size)
{
    const float* x      = (const float*)d_in[0];
    const float* w      = (const float*)d_in[1];
    const float* cb     = (const float*)d_in[2];
    const float* fg     = (const float*)d_in[3];
    const float* ag     = (const float*)d_in[4];
    const float* ab     = (const float*)d_in[5];
    const float* og     = (const float*)d_in[6];
    const float* ob     = (const float*)d_in[7];
    const float* pg     = (const float*)d_in[8];
    const float* pb     = (const float*)d_in[9];
    const float* bw     = (const float*)d_in[10];
    const float* wrow   = (const float*)d_in[11];
    const float* wcol   = (const float*)d_in[12];
    const float* palpha = (const float*)d_in[13];
    const float* pbias  = (const float*)d_in[14];
    float* out = (float*)d_out;

    const int FLASH_SMEM = (64 * 65 + 64 * 64 + 64 * 64) * 4;                          // 49408
    const int LIN_SMEM   = (64 * 65 + 64 * 64 + 64 * 32 + 64 * 65 + 64 * 36 + 64) * 4; // 67328
    cudaFuncSetAttribute(flash_kernel, cudaFuncAttributeMaxDynamicSharedMemorySize, FLASH_SMEM);
    cudaFuncSetAttribute(linear_kernel, cudaFuncAttributeMaxDynamicSharedMemorySize, LIN_SMEM);

    split_kernel<<<1024, 256>>>(x, w);
    qkv_mma_kernel<<<dim3(M3_ / 128, NROW_ / 128), 256>>>(cb);
    flash_kernel<<<dim3(T_ / 64, B_ * H_), 256, FLASH_SMEM>>>();
    linear_kernel<<<B_ * H_ * 2, 256, LIN_SMEM>>>();
    combine_kernel<<<NROW_, 256>>>(fg, ag, ab, og, ob, pg, pb, bw, wrow, wcol,
                                   palpha, pbias, out);
}

// round 12
// speedup vs baseline: 1.4145x; 1.1104x over previous
#include <cuda_runtime.h>
#include <cuda_bf16.h>
#include <math.h>
#include <stdint.h>

#define B_ 2
#define T_ 1024
#define C_ 1024
#define H_ 16
#define D_ 64
#define NROW_ (B_*T_)     // 2048
#define M3_ (3*C_)        // 3072

// ---------------- device scratch (static, no allocation) ----------------
__device__ float g_qkv[NROW_ * M3_];            // 25.2 MB
__device__ float g_ylin[NROW_ * C_];            // 8.4 MB
__device__ float g_ysharp[NROW_ * C_];          // 8.4 MB
__device__ __nv_bfloat16 g_xhi[NROW_ * C_];     // 4.2 MB
__device__ __nv_bfloat16 g_xlo[NROW_ * C_];     // 4.2 MB
__device__ __nv_bfloat16 g_whi[M3_ * C_];       // 6.3 MB
__device__ __nv_bfloat16 g_wlo[M3_ * C_];       // 6.3 MB
// linear-attention chunked state scratch
__device__ float g_cs[32 * 16 * 4096];          // 8.4 MB per-chunk Kp^T@V
__device__ float g_ck[32 * 16 * 64];            // per-chunk sum Kp
__device__ float g_sprev[32 * 16 * 4096];       // 8.4 MB exclusive prefix state
__device__ float g_ckprev[32 * 16 * 64];        // exclusive prefix ksum

__device__ __forceinline__ float elup(float x) {
    return x > 0.f ? x + 1.f : __expf(x);
}

__device__ __forceinline__ uint32_t smem_u32(const void* p) {
    uint32_t a;
    asm("{ .reg .u64 t; cvta.to.shared.u64 t, %1; cvt.u32.u64 %0, t; }" : "=r"(a) : "l"(p));
    return a;
}
__device__ __forceinline__ void ldm_x4(uint32_t a[4], uint32_t addr) {
    asm volatile("ldmatrix.sync.aligned.m8n8.x4.shared.b16 {%0,%1,%2,%3}, [%4];"
                 : "=r"(a[0]), "=r"(a[1]), "=r"(a[2]), "=r"(a[3]) : "r"(addr));
}
__device__ __forceinline__ void ldm_x2(uint32_t a[2], uint32_t addr) {
    asm volatile("ldmatrix.sync.aligned.m8n8.x2.shared.b16 {%0,%1}, [%2];"
                 : "=r"(a[0]), "=r"(a[1]) : "r"(addr));
}
__device__ __forceinline__ void mma16816(float c[4], const uint32_t a[4], const uint32_t b[2]) {
    asm volatile("mma.sync.aligned.m16n8k16.row.col.f32.bf16.bf16.f32 "
                 "{%0,%1,%2,%3}, {%4,%5,%6,%7}, {%8,%9}, {%0,%1,%2,%3};"
                 : "+f"(c[0]), "+f"(c[1]), "+f"(c[2]), "+f"(c[3])
                 : "r"(a[0]), "r"(a[1]), "r"(a[2]), "r"(a[3]), "r"(b[0]), "r"(b[1]));
}

// ---------------- Kernel 0: hi/lo bf16 split (float4 streaming) ----------------
__global__ void __launch_bounds__(256) split_kernel(const float* __restrict__ X,
                                                    const float* __restrict__ W)
{
    int nx4 = NROW_ * C_ / 4;
    int nw4 = M3_ * C_ / 4;
    int tot = nx4 + nw4;
    for (int idx = blockIdx.x * 256 + threadIdx.x; idx < tot; idx += gridDim.x * 256) {
        const float4 v = (idx < nx4) ? ((const float4*)X)[idx]
                                     : ((const float4*)W)[idx - nx4];
        float e[4] = {v.x, v.y, v.z, v.w};
        __nv_bfloat16 hi[4], lo[4];
#pragma unroll
        for (int k = 0; k < 4; k++) {
            hi[k] = __float2bfloat16(e[k]);
            lo[k] = __float2bfloat16(e[k] - __bfloat162float(hi[k]));
        }
        if (idx < nx4) {
            ((uint2*)g_xhi)[idx] = *(uint2*)hi;
            ((uint2*)g_xlo)[idx] = *(uint2*)lo;
        } else {
            ((uint2*)g_whi)[idx - nx4] = *(uint2*)hi;
            ((uint2*)g_wlo)[idx - nx4] = *(uint2*)lo;
        }
    }
}

// ---------------- Kernel 1: QKV GEMM via mma.sync bf16 hi/lo ----------------
#define ROWB 80

__global__ void __launch_bounds__(256) qkv_mma_kernel(const float* __restrict__ bias)
{
    __shared__ __align__(16) char sXhi[128 * ROWB];
    __shared__ __align__(16) char sXlo[128 * ROWB];
    __shared__ __align__(16) char sWhi[128 * ROWB];
    __shared__ __align__(16) char sWlo[128 * ROWB];

    int tid = threadIdx.x;
    int wid = tid >> 5, lane = tid & 31;
    int wm = wid >> 2, wn = wid & 3;
    int n0 = blockIdx.y * 128;
    int m0 = blockIdx.x * 128;

    uint32_t bXhi = smem_u32(sXhi), bXlo = smem_u32(sXlo);
    uint32_t bWhi = smem_u32(sWhi), bWlo = smem_u32(sWlo);

    float acc[4][4][4];
#pragma unroll
    for (int mt = 0; mt < 4; mt++)
#pragma unroll
        for (int nt = 0; nt < 4; nt++)
#pragma unroll
            for (int k = 0; k < 4; k++) acc[mt][nt][k] = 0.f;

    int a_mat = lane >> 3, a_row = lane & 7;
    int a_roff = ((a_mat & 1) << 3) + a_row;
    int a_uoff = a_mat >> 1;
    int b_row = lane & 7;
    int b_uoff = (lane >> 3) & 1;

    for (int kc = 0; kc < 32; kc++) {
#pragma unroll
        for (int it = 0; it < 2; it++) {
            int l = tid + it * 256;
            int r = l >> 2, u = l & 3;
            uint32_t off = r * ROWB + u * 16;
            int gx = (n0 + r) * C_ + kc * 32 + u * 8;
            int gw = (m0 + r) * C_ + kc * 32 + u * 8;
            *(uint4*)(sXhi + off) = *(const uint4*)(g_xhi + gx);
            *(uint4*)(sXlo + off) = *(const uint4*)(g_xlo + gx);
            *(uint4*)(sWhi + off) = *(const uint4*)(g_whi + gw);
            *(uint4*)(sWlo + off) = *(const uint4*)(g_wlo + gw);
        }
        __syncthreads();

#pragma unroll
        for (int ks = 0; ks < 2; ks++) {
            uint32_t ahi[4][4], alo[4][4];
#pragma unroll
            for (int mt = 0; mt < 4; mt++) {
                int r = wm * 64 + mt * 16 + a_roff;
                uint32_t off = r * ROWB + (ks * 2 + a_uoff) * 16;
                ldm_x4(ahi[mt], bXhi + off);
                ldm_x4(alo[mt], bXlo + off);
            }
            uint32_t bhi[4][2], blo[4][2];
#pragma unroll
            for (int nt = 0; nt < 4; nt++) {
                int r = wn * 32 + nt * 8 + b_row;
                uint32_t off = r * ROWB + (ks * 2 + b_uoff) * 16;
                ldm_x2(bhi[nt], bWhi + off);
                ldm_x2(blo[nt], bWlo + off);
            }
#pragma unroll
            for (int mt = 0; mt < 4; mt++)
#pragma unroll
                for (int nt = 0; nt < 4; nt++) {
                    mma16816(acc[mt][nt], ahi[mt], bhi[nt]);
                    mma16816(acc[mt][nt], ahi[mt], blo[nt]);
                    mma16816(acc[mt][nt], alo[mt], bhi[nt]);
                }
        }
        __syncthreads();
    }

    int g = lane >> 2, tg = lane & 3;
#pragma unroll
    for (int mt = 0; mt < 4; mt++) {
        int r0 = n0 + wm * 64 + mt * 16 + g;
#pragma unroll
        for (int nt = 0; nt < 4; nt++) {
            int c = m0 + wn * 32 + nt * 8 + tg * 2;
            float b0 = bias[c], b1 = bias[c + 1];
            *(float2*)(g_qkv + r0 * M3_ + c) =
                make_float2(acc[mt][nt][0] + b0, acc[mt][nt][1] + b1);
            *(float2*)(g_qkv + (r0 + 8) * M3_ + c) =
                make_float2(acc[mt][nt][2] + b0, acc[mt][nt][3] + b1);
        }
    }
}

// ---------------- Kernel 2: causal softmax attention (flash-style) ----------------
__global__ void __launch_bounds__(256) flash_kernel()
{
    extern __shared__ float sm[];
    float* Q = sm;                 // 64 x 65
    float* K = Q + 64 * 65;        // 64 x 64 (float4-swizzled)
    float* V = K + 64 * 64;        // 64 x 64

    int qt = blockIdx.x, bh = blockIdx.y;
    int b = bh >> 4, h = bh & 15;
    int tid = threadIdx.x;
    int i = tid >> 2, lane4 = tid & 3;
    int lbase = (tid & 31) & ~3;
    int e0 = lane4 * 16;

    for (int l = tid; l < 64 * 64; l += 256) {
        int r = l >> 6, d = l & 63;
        Q[r * 65 + d] = g_qkv[(b * T_ + qt * 64 + r) * M3_ + h * 64 + d];
    }

    float acc[16];
#pragma unroll
    for (int e = 0; e < 16; e++) acc[e] = 0.f;
    float m_prev = -1e30f, l_sum = 0.f;

    for (int kt = 0; kt <= qt; kt++) {
        __syncthreads();
        for (int l = tid; l < 64 * 64; l += 256) {
            int r = l >> 6, d = l & 63;
            int gidx = (b * T_ + kt * 64 + r) * M3_ + h * 64 + d;
            int d4 = d >> 2;
            K[r * 64 + ((d4 ^ (r & 3)) << 2) + (d & 3)] = g_qkv[gidx + C_];
            V[r * 64 + d] = g_qkv[gidx + 2 * C_];
        }
        __syncthreads();

        float s[16];
#pragma unroll
        for (int jj = 0; jj < 16; jj++) s[jj] = 0.f;
        const float4* Kv = (const float4*)K;
#pragma unroll
        for (int d4 = 0; d4 < 16; d4++) {
            float q0 = Q[i * 65 + 4 * d4 + 0];
            float q1 = Q[i * 65 + 4 * d4 + 1];
            float q2 = Q[i * 65 + 4 * d4 + 2];
            float q3 = Q[i * 65 + 4 * d4 + 3];
#pragma unroll
            for (int jj = 0; jj < 16; jj++) {
                int j = 4 * jj + lane4;
                float4 kv = Kv[j * 16 + (d4 ^ lane4)];
                s[jj] += q0 * kv.x + q1 * kv.y + q2 * kv.z + q3 * kv.w;
            }
        }
        bool diag = (kt == qt);
        float mloc = -1e30f;
#pragma unroll
        for (int jj = 0; jj < 16; jj++) {
            int j = 4 * jj + lane4;
            float sv = s[jj] * 0.125f;
            if (diag && j > i) sv = -1e30f;
            s[jj] = sv;
            mloc = fmaxf(mloc, sv);
        }
        mloc = fmaxf(mloc, __shfl_xor_sync(0xffffffffu, mloc, 1));
        mloc = fmaxf(mloc, __shfl_xor_sync(0xffffffffu, mloc, 2));
        float m_new = fmaxf(m_prev, mloc);
        float corr = __expf(m_prev - m_new);
        float p[16];
        float psum = 0.f;
#pragma unroll
        for (int jj = 0; jj < 16; jj++) {
            p[jj] = __expf(s[jj] - m_new);
            psum += p[jj];
        }
        psum += __shfl_xor_sync(0xffffffffu, psum, 1);
        psum += __shfl_xor_sync(0xffffffffu, psum, 2);
        l_sum = l_sum * corr + psum;
        m_prev = m_new;
#pragma unroll
        for (int e = 0; e < 16; e++) acc[e] *= corr;

        const float4* Vv = (const float4*)V;
#pragma unroll
        for (int jj = 0; jj < 16; jj++) {
            float pj = p[jj];
#pragma unroll
            for (int l = 0; l < 4; l++) {
                float pb = __shfl_sync(0xffffffffu, pj, lbase + l);
                int j = 4 * jj + l;
#pragma unroll
                for (int e4 = 0; e4 < 4; e4++) {
                    float4 vv = Vv[j * 16 + lane4 * 4 + e4];
                    acc[e4 * 4 + 0] = fmaf(pb, vv.x, acc[e4 * 4 + 0]);
                    acc[e4 * 4 + 1] = fmaf(pb, vv.y, acc[e4 * 4 + 1]);
                    acc[e4 * 4 + 2] = fmaf(pb, vv.z, acc[e4 * 4 + 2]);
                    acc[e4 * 4 + 3] = fmaf(pb, vv.w, acc[e4 * 4 + 3]);
                }
            }
        }
    }
    float inv = 1.f / l_sum;
    int orow = (b * T_ + qt * 64 + i) * C_ + h * 64 + e0;
#pragma unroll
    for (int e = 0; e < 16; e++)
        g_ysharp[orow + e] = acc[e] * inv;
}

// ---------------- Kernel 3a: per-chunk state contribution C = Kp^T @ V ----------------
// grid (16 ch, 32 bh), 256 threads. Thread: d = tid>>2, e-slices k*16 + lane4*4 + c.
__global__ void __launch_bounds__(256) chunk_state_kernel()
{
    __shared__ float KPT[64 * 65];   // transposed Kp: [d][r]
    __shared__ float V[64 * 64];

    int ch = blockIdx.x, bh = blockIdx.y;
    int b = bh >> 4, h = bh & 15;
    int tid = threadIdx.x;
    int d = tid >> 2, lane4 = tid & 3;

    for (int l = tid; l < 64 * 64; l += 256) {
        int r = l >> 6, dd = l & 63;
        int gidx = (b * T_ + ch * 64 + r) * M3_ + h * 64 + dd;
        KPT[dd * 65 + r] = elup(g_qkv[gidx + C_] * 0.125f);
        V[r * 64 + dd]   = g_qkv[gidx + 2 * C_];
    }
    __syncthreads();

    float acc[16];
#pragma unroll
    for (int e = 0; e < 16; e++) acc[e] = 0.f;
    float ks = 0.f;
    const float4* Vv = (const float4*)V;
#pragma unroll 8
    for (int j = 0; j < 64; j++) {
        float kp = KPT[d * 65 + j];
        ks += kp;
#pragma unroll
        for (int k = 0; k < 4; k++) {
            float4 vv = Vv[j * 16 + k * 4 + lane4];
            acc[k * 4 + 0] = fmaf(kp, vv.x, acc[k * 4 + 0]);
            acc[k * 4 + 1] = fmaf(kp, vv.y, acc[k * 4 + 1]);
            acc[k * 4 + 2] = fmaf(kp, vv.z, acc[k * 4 + 2]);
            acc[k * 4 + 3] = fmaf(kp, vv.w, acc[k * 4 + 3]);
        }
    }
    float* cs = g_cs + (bh * 16 + ch) * 4096 + d * 64;
#pragma unroll
    for (int k = 0; k < 4; k++)
        *(float4*)(cs + k * 16 + lane4 * 4) =
            make_float4(acc[k * 4 + 0], acc[k * 4 + 1], acc[k * 4 + 2], acc[k * 4 + 3]);
    if (lane4 == 0) g_ck[(bh * 16 + ch) * 64 + d] = ks;
}

// ---------------- Kernel 3b: exclusive prefix over chunks ----------------
__global__ void __launch_bounds__(256) prefix_kernel()
{
    int bh = blockIdx.x;
    for (int idx = threadIdx.x; idx < 4096; idx += 256) {
        float run = 0.f;
#pragma unroll
        for (int ch = 0; ch < 16; ch++) {
            int o = (bh * 16 + ch) * 4096 + idx;
            g_sprev[o] = run;
            run += g_cs[o];
        }
    }
    if (threadIdx.x < 64) {
        int idx = threadIdx.x;
        float run = 0.f;
#pragma unroll
        for (int ch = 0; ch < 16; ch++) {
            int o = (bh * 16 + ch) * 64 + idx;
            g_ckprev[o] = run;
            run += g_ck[o];
        }
    }
}

// ---------------- Kernel 3c: linear attention output (fully parallel) ----------------
// grid (16 ch, 32 bh), 256 threads. Thread: row i = tid>>2, e-slices k*16 + lane4*4 + c.
__global__ void __launch_bounds__(256) linear_out_kernel()
{
    extern __shared__ float sm[];
    float* QP = sm;                // 64 x 65
    float* KP = QP + 64 * 65;      // 64 x 64 (swizzled)
    float* V  = KP + 64 * 64;      // 64 x 64
    float* P  = V + 64 * 64;       // 64 x 65
    float* SP = P + 64 * 65;       // 64 x 68 (state rows padded)
    float* kc = SP + 64 * 68;      // 64

    int ch = blockIdx.x, bh = blockIdx.y;
    int b = bh >> 4, h = bh & 15;
    int tid = threadIdx.x;
    int i = tid >> 2, lane4 = tid & 3;

    for (int l = tid; l < 64 * 64; l += 256) {
        int r = l >> 6, d = l & 63;
        int gidx = (b * T_ + ch * 64 + r) * M3_ + h * 64 + d;
        QP[r * 65 + d] = elup(g_qkv[gidx] * 0.125f);
        int d4 = d >> 2;
        KP[r * 64 + ((d4 ^ (r & 3)) << 2) + (d & 3)] = elup(g_qkv[gidx + C_] * 0.125f);
        V[r * 64 + d] = g_qkv[gidx + 2 * C_];
        SP[r * 68 + d] = g_sprev[(bh * 16 + ch) * 4096 + r * 64 + d];
    }
    if (tid < 64) kc[tid] = g_ckprev[(bh * 16 + ch) * 64 + tid];
    __syncthreads();

    // intra-chunk scores: lane owns j = 4*jj + lane4
    float s[16];
#pragma unroll
    for (int jj = 0; jj < 16; jj++) s[jj] = 0.f;
    const float4* Kv = (const float4*)KP;
#pragma unroll
    for (int d4 = 0; d4 < 16; d4++) {
        float q0 = QP[i * 65 + 4 * d4 + 0];
        float q1 = QP[i * 65 + 4 * d4 + 1];
        float q2 = QP[i * 65 + 4 * d4 + 2];
        float q3 = QP[i * 65 + 4 * d4 + 3];
#pragma unroll
        for (int jj = 0; jj < 16; jj++) {
            int j = 4 * jj + lane4;
            float4 kv = Kv[j * 16 + (d4 ^ lane4)];
            s[jj] += q0 * kv.x + q1 * kv.y + q2 * kv.z + q3 * kv.w;
        }
    }
    float psum = 0.f;
#pragma unroll
    for (int jj = 0; jj < 16; jj++) {
        int j = 4 * jj + lane4;
        float sv = (j <= i) ? s[jj] : 0.f;
        P[i * 65 + j] = sv;
        psum += sv;
    }
    float dpart = 0.f;
#pragma unroll
    for (int dd = 0; dd < 16; dd++)
        dpart += QP[i * 65 + lane4 * 16 + dd] * kc[lane4 * 16 + dd];
    float den = psum + dpart;
    den += __shfl_xor_sync(0xffffffffu, den, 1);
    den += __shfl_xor_sync(0xffffffffu, den, 2);
    den += 1e-4f;

    // numer = Qp_i @ S_prev  +  P_i @ V  (16 e per thread: e = k*16 + lane4*4 + c)
    float num[16];
#pragma unroll
    for (int e = 0; e < 16; e++) num[e] = 0.f;
    const float4* SPv = (const float4*)SP;   // row stride 17 float4
#pragma unroll 8
    for (int d = 0; d < 64; d++) {
        float q = QP[i * 65 + d];
#pragma unroll
        for (int k = 0; k < 4; k++) {
            float4 sp = SPv[d * 17 + k * 4 + lane4];
            num[k * 4 + 0] = fmaf(q, sp.x, num[k * 4 + 0]);
            num[k * 4 + 1] = fmaf(q, sp.y, num[k * 4 + 1]);
            num[k * 4 + 2] = fmaf(q, sp.z, num[k * 4 + 2]);
            num[k * 4 + 3] = fmaf(q, sp.w, num[k * 4 + 3]);
        }
    }
    __syncwarp();
    const float4* Vv = (const float4*)V;
#pragma unroll 8
    for (int j = 0; j < 64; j++) {
        float pv = P[i * 65 + j];
#pragma unroll
        for (int k = 0; k < 4; k++) {
            float4 vv = Vv[j * 16 + k * 4 + lane4];
            num[k * 4 + 0] = fmaf(pv, vv.x, num[k * 4 + 0]);
            num[k * 4 + 1] = fmaf(pv, vv.y, num[k * 4 + 1]);
            num[k * 4 + 2] = fmaf(pv, vv.z, num[k * 4 + 2]);
            num[k * 4 + 3] = fmaf(pv, vv.w, num[k * 4 + 3]);
        }
    }
    float invd = 1.f / den;
    float* orow = g_ylin + (b * T_ + ch * 64 + i) * C_ + h * 64;
#pragma unroll
    for (int k = 0; k < 4; k++)
        *(float4*)(orow + k * 16 + lane4 * 4) =
            make_float4(num[k * 4 + 0] * invd, num[k * 4 + 1] * invd,
                        num[k * 4 + 2] * invd, num[k * 4 + 3] * invd);
}

// ---------------- Kernel 4: combine (vectorized float4) ----------------
__device__ __forceinline__ void block_ln_stats(float lsum, float lsq, float* red,
                                               float* mean, float* rstd)
{
#pragma unroll
    for (int m = 16; m >= 1; m >>= 1) {
        lsum += __shfl_xor_sync(0xffffffffu, lsum, m);
        lsq  += __shfl_xor_sync(0xffffffffu, lsq, m);
    }
    int w = threadIdx.x >> 5;
    if ((threadIdx.x & 31) == 0) { red[w] = lsum; red[8 + w] = lsq; }
    __syncthreads();
    if (threadIdx.x == 0) {
        float s = 0.f, q = 0.f;
#pragma unroll
        for (int k = 0; k < 8; k++) { s += red[k]; q += red[8 + k]; }
        float mu = s * (1.f / 1024.f);
        red[16] = mu;
        red[17] = rsqrtf(q * (1.f / 1024.f) - mu * mu + 1e-5f);
    }
    __syncthreads();
    *mean = red[16];
    *rstd = red[17];
}

__global__ void __launch_bounds__(256) combine_kernel(
    const float* __restrict__ fg,
    const float* __restrict__ attn_g, const float* __restrict__ attn_b,
    const float* __restrict__ out_g,  const float* __restrict__ out_b,
    const float* __restrict__ pre_g,  const float* __restrict__ pre_b,
    const float* __restrict__ bw,     const float* __restrict__ wrow,
    const float* __restrict__ wcol,   const float* __restrict__ palpha,
    const float* __restrict__ pbias,  float* __restrict__ out)
{
    __shared__ float sx[1024];
    __shared__ float sy[1024];
    __shared__ float sz[1024];
    __shared__ float red[32];

    int n = blockIdx.x, tid = threadIdx.x;
    int c0 = tid * 4;
    float afg = 1.f / (1.f + __expf(-fg[0]));

    float4 ylv = *(const float4*)(g_ylin + n * C_ + c0);
    float4 ysv = *(const float4*)(g_ysharp + n * C_ + c0);
    float yl[4] = {ylv.x, ylv.y, ylv.z, ylv.w};
    float ys[4] = {ysv.x, ysv.y, ysv.z, ysv.w};
    float yv[4];
    float hsum = 0.f, hsq = 0.f;
#pragma unroll
    for (int k = 0; k < 4; k++) { hsum += yl[k]; hsq += yl[k] * yl[k]; }
#pragma unroll
    for (int m = 1; m < 16; m <<= 1) {
        hsum += __shfl_xor_sync(0xffffffffu, hsum, m);
        hsq  += __shfl_xor_sync(0xffffffffu, hsq, m);
    }
    float hmean = hsum * (1.f / 64.f);
    float hrstd = rsqrtf(hsq * (1.f / 64.f) - hmean * hmean + 1e-5f);
#pragma unroll
    for (int k = 0; k < 4; k++) {
        int d = (c0 + k) & 63;
        float v = (yl[k] - hmean) * hrstd * attn_g[d] + attn_b[d];
        yv[k] = afg * ys[k] + (1.f - afg) * v;
    }

    float lsum = 0.f, lsq = 0.f;
#pragma unroll
    for (int k = 0; k < 4; k++) { lsum += yv[k]; lsq += yv[k] * yv[k]; }
    float mu, rs;
    block_ln_stats(lsum, lsq, red, &mu, &rs);
#pragma unroll
    for (int k = 0; k < 4; k++)
        yv[k] = (yv[k] - mu) * rs * out_g[c0 + k] + out_b[c0 + k];

    lsum = 0.f; lsq = 0.f;
#pragma unroll
    for (int k = 0; k < 4; k++) { lsum += yv[k]; lsq += yv[k] * yv[k]; }
    block_ln_stats(lsum, lsq, red, &mu, &rs);
#pragma unroll
    for (int k = 0; k < 4; k++)
        sx[c0 + k] = (yv[k] - mu) * rs * pre_g[c0 + k] + pre_b[c0 + k];
    __syncthreads();

    const float4* sx4 = (const float4*)sx;

    int g = c0 >> 4, j0 = c0 & 15;
    float4 ymv = make_float4(0.f, 0.f, 0.f, 0.f);
#pragma unroll
    for (int ii4 = 0; ii4 < 4; ii4++) {
        float4 sxv = sx4[g * 4 + ii4];
        float sxe[4] = {sxv.x, sxv.y, sxv.z, sxv.w};
#pragma unroll
        for (int t = 0; t < 4; t++) {
            int ii = ii4 * 4 + t;
            float4 bwv = *(const float4*)(bw + g * 256 + ii * 16 + j0);
            ymv.x = fmaf(sxe[t], bwv.x, ymv.x);
            ymv.y = fmaf(sxe[t], bwv.y, ymv.y);
            ymv.z = fmaf(sxe[t], bwv.z, ymv.z);
            ymv.w = fmaf(sxe[t], bwv.w, ymv.w);
        }
    }

    int gi = c0 >> 5, cc0 = c0 & 31;
    float4 zvv = make_float4(0.f, 0.f, 0.f, 0.f);
#pragma unroll
    for (int jj4 = 0; jj4 < 8; jj4++) {
        float4 sxv = sx4[gi * 8 + jj4];
        float sxe[4] = {sxv.x, sxv.y, sxv.z, sxv.w};
#pragma unroll
        for (int t = 0; t < 4; t++) {
            int jj = jj4 * 4 + t;
            float4 wcv = *(const float4*)(wcol + jj * 32 + cc0);
            zvv.x = fmaf(sxe[t], wcv.x, zvv.x);
            zvv.y = fmaf(sxe[t], wcv.y, zvv.y);
            zvv.z = fmaf(sxe[t], wcv.z, zvv.z);
            zvv.w = fmaf(sxe[t], wcv.w, zvv.w);
        }
    }
    *(float4*)(sy + c0) = ymv;
    *(float4*)(sz + c0) = zvv;
    __syncthreads();

    const float4* sz4 = (const float4*)sz;
    int r0 = c0 & 31;
    float zz[4] = {0.f, 0.f, 0.f, 0.f};
#pragma unroll
    for (int cc4 = 0; cc4 < 8; cc4++) {
        float4 szv = sz4[gi * 8 + cc4];
#pragma unroll
        for (int k = 0; k < 4; k++) {
            float4 wrv = *(const float4*)(wrow + (r0 + k) * 32 + cc4 * 4);
            zz[k] += szv.x * wrv.x + szv.y * wrv.y + szv.z * wrv.z + szv.w * wrv.w;
        }
    }

    float pa = palpha[0];
    float4 pbv = *(const float4*)(pbias + c0);
    float pbe[4] = {pbv.x, pbv.y, pbv.z, pbv.w};
#pragma unroll
    for (int k = 0; k < 4; k++) {
        int c = c0 + k;
        out[n * C_ + c] = sy[1023 - c] + pa * zz[k] + pbe[k];
    }
}

// ---------------- launch ----------------
extern "C" void kernel_launch(void* const* d_in, const int* in_sizes, int n_in,
                              void* d_out, int out_size)
{
    const float* x      = (const float*)d_in[0];
    const float* w      = (const float*)d_in[1];
    const float* cb     = (const float*)d_in[2];
    const float* fg     = (const float*)d_in[3];
    const float* ag     = (const float*)d_in[4];
    const float* ab     = (const float*)d_in[5];
    const float* og     = (const float*)d_in[6];
    const float* ob     = (const float*)d_in[7];
    const float* pg     = (const float*)d_in[8];
    const float* pb     = (const float*)d_in[9];
    const float* bw     = (const float*)d_in[10];
    const float* wrow   = (const float*)d_in[11];
    const float* wcol   = (const float*)d_in[12];
    const float* palpha = (const float*)d_in[13];
    const float* pbias  = (const float*)d_in[14];
    float* out = (float*)d_out;

    const int FLASH_SMEM = (64 * 65 + 64 * 64 + 64 * 64) * 4;                          // 49408
    const int LINOUT_SMEM = (64 * 65 + 64 * 64 + 64 * 64 + 64 * 65 + 64 * 68 + 64) * 4; // 83712
    cudaFuncSetAttribute(flash_kernel, cudaFuncAttributeMaxDynamicSharedMemorySize, FLASH_SMEM);
    cudaFuncSetAttribute(linear_out_kernel, cudaFuncAttributeMaxDynamicSharedMemorySize, LINOUT_SMEM);

    split_kernel<<<1024, 256>>>(x, w);
    qkv_mma_kernel<<<dim3(M3_ / 128, NROW_ / 128), 256>>>(cb);
    flash_kernel<<<dim3(T_ / 64, B_ * H_), 256, FLASH_SMEM>>>();
    chunk_state_kernel<<<dim3(16, 32), 256>>>();
    prefix_kernel<<<32, 256>>>();
    linear_out_kernel<<<dim3(16, 32), 256, LINOUT_SMEM>>>();
    combine_kernel<<<NROW_, 256>>>(fg, ag, ab, og, ob, pg, pb, bw, wrow, wcol,
                                   palpha, pbias, out);
}

// round 15
// speedup vs baseline: 2.8203x; 1.9939x over previous
#include <cuda_runtime.h>
#include <cuda_bf16.h>
#include <math.h>
#include <stdint.h>

#define B_ 2
#define T_ 1024
#define C_ 1024
#define H_ 16
#define D_ 64
#define NROW_ (B_*T_)     // 2048
#define M3_ (3*C_)        // 3072

// ---------------- device scratch (static, no allocation) ----------------
__device__ float g_qkv[NROW_ * M3_];            // 25.2 MB
__device__ float g_ylin[NROW_ * C_];            // 8.4 MB
__device__ float g_ysharp[NROW_ * C_];          // 8.4 MB
__device__ __nv_bfloat16 g_xhi[NROW_ * C_];     // 4.2 MB
__device__ __nv_bfloat16 g_xlo[NROW_ * C_];     // 4.2 MB
__device__ __nv_bfloat16 g_whi[M3_ * C_];       // 6.3 MB
__device__ __nv_bfloat16 g_wlo[M3_ * C_];       // 6.3 MB
// linear-attention chunked state scratch
__device__ float g_cs[32 * 16 * 4096];          // 8.4 MB per-chunk Kp^T@V
__device__ float g_ck[32 * 16 * 64];
__device__ float g_sprev[32 * 16 * 4096];       // 8.4 MB exclusive prefix state
__device__ float g_ckprev[32 * 16 * 64];

__device__ __forceinline__ float elup(float x) {
    return x > 0.f ? x + 1.f : __expf(x);
}

__device__ __forceinline__ uint32_t smem_u32(const void* p) {
    uint32_t a;
    asm("{ .reg .u64 t; cvta.to.shared.u64 t, %1; cvt.u32.u64 %0, t; }" : "=r"(a) : "l"(p));
    return a;
}
__device__ __forceinline__ void ldm_x4(uint32_t a[4], uint32_t addr) {
    asm volatile("ldmatrix.sync.aligned.m8n8.x4.shared.b16 {%0,%1,%2,%3}, [%4];"
                 : "=r"(a[0]), "=r"(a[1]), "=r"(a[2]), "=r"(a[3]) : "r"(addr));
}
__device__ __forceinline__ void ldm_x2(uint32_t a[2], uint32_t addr) {
    asm volatile("ldmatrix.sync.aligned.m8n8.x2.shared.b16 {%0,%1}, [%2];"
                 : "=r"(a[0]), "=r"(a[1]) : "r"(addr));
}
__device__ __forceinline__ void ldm_x2_trans(uint32_t a[2], uint32_t addr) {
    asm volatile("ldmatrix.sync.aligned.m8n8.x2.trans.shared.b16 {%0,%1}, [%2];"
                 : "=r"(a[0]), "=r"(a[1]) : "r"(addr));
}
__device__ __forceinline__ void mma16816(float c[4], const uint32_t a[4], const uint32_t b[2]) {
    asm volatile("mma.sync.aligned.m16n8k16.row.col.f32.bf16.bf16.f32 "
                 "{%0,%1,%2,%3}, {%4,%5,%6,%7}, {%8,%9}, {%0,%1,%2,%3};"
                 : "+f"(c[0]), "+f"(c[1]), "+f"(c[2]), "+f"(c[3])
                 : "r"(a[0]), "r"(a[1]), "r"(a[2]), "r"(a[3]), "r"(b[0]), "r"(b[1]));
}
__device__ __forceinline__ uint32_t pack_bf16(float x, float y) {
    __nv_bfloat162 t = __floats2bfloat162_rn(x, y);
    return *(uint32_t*)&t;
}

// ---------------- Kernel 0: hi/lo bf16 split (float4 streaming) ----------------
__global__ void __launch_bounds__(256) split_kernel(const float* __restrict__ X,
                                                    const float* __restrict__ W)
{
    int nx4 = NROW_ * C_ / 4;
    int nw4 = M3_ * C_ / 4;
    int tot = nx4 + nw4;
    for (int idx = blockIdx.x * 256 + threadIdx.x; idx < tot; idx += gridDim.x * 256) {
        const float4 v = (idx < nx4) ? ((const float4*)X)[idx]
                                     : ((const float4*)W)[idx - nx4];
        float e[4] = {v.x, v.y, v.z, v.w};
        __nv_bfloat16 hi[4], lo[4];
#pragma unroll
        for (int k = 0; k < 4; k++) {
            hi[k] = __float2bfloat16(e[k]);
            lo[k] = __float2bfloat16(e[k] - __bfloat162float(hi[k]));
        }
        if (idx < nx4) {
            ((uint2*)g_xhi)[idx] = *(uint2*)hi;
            ((uint2*)g_xlo)[idx] = *(uint2*)lo;
        } else {
            ((uint2*)g_whi)[idx - nx4] = *(uint2*)hi;
            ((uint2*)g_wlo)[idx - nx4] = *(uint2*)lo;
        }
    }
}

// ---------------- Kernel 1: QKV GEMM via mma.sync bf16 hi/lo ----------------
#define ROWB 80

__global__ void __launch_bounds__(256) qkv_mma_kernel(const float* __restrict__ bias)
{
    __shared__ __align__(16) char sXhi[128 * ROWB];
    __shared__ __align__(16) char sXlo[128 * ROWB];
    __shared__ __align__(16) char sWhi[128 * ROWB];
    __shared__ __align__(16) char sWlo[128 * ROWB];

    int tid = threadIdx.x;
    int wid = tid >> 5, lane = tid & 31;
    int wm = wid >> 2, wn = wid & 3;
    int n0 = blockIdx.y * 128;
    int m0 = blockIdx.x * 128;

    uint32_t bXhi = smem_u32(sXhi), bXlo = smem_u32(sXlo);
    uint32_t bWhi = smem_u32(sWhi), bWlo = smem_u32(sWlo);

    float acc[4][4][4];
#pragma unroll
    for (int mt = 0; mt < 4; mt++)
#pragma unroll
        for (int nt = 0; nt < 4; nt++)
#pragma unroll
            for (int k = 0; k < 4; k++) acc[mt][nt][k] = 0.f;

    int a_mat = lane >> 3, a_row = lane & 7;
    int a_roff = ((a_mat & 1) << 3) + a_row;
    int a_uoff = a_mat >> 1;
    int b_row = lane & 7;
    int b_uoff = (lane >> 3) & 1;

    for (int kc = 0; kc < 32; kc++) {
#pragma unroll
        for (int it = 0; it < 2; it++) {
            int l = tid + it * 256;
            int r = l >> 2, u = l & 3;
            uint32_t off = r * ROWB + u * 16;
            int gx = (n0 + r) * C_ + kc * 32 + u * 8;
            int gw = (m0 + r) * C_ + kc * 32 + u * 8;
            *(uint4*)(sXhi + off) = *(const uint4*)(g_xhi + gx);
            *(uint4*)(sXlo + off) = *(const uint4*)(g_xlo + gx);
            *(uint4*)(sWhi + off) = *(const uint4*)(g_whi + gw);
            *(uint4*)(sWlo + off) = *(const uint4*)(g_wlo + gw);
        }
        __syncthreads();

#pragma unroll
        for (int ks = 0; ks < 2; ks++) {
            uint32_t ahi[4][4], alo[4][4];
#pragma unroll
            for (int mt = 0; mt < 4; mt++) {
                int r = wm * 64 + mt * 16 + a_roff;
                uint32_t off = r * ROWB + (ks * 2 + a_uoff) * 16;
                ldm_x4(ahi[mt], bXhi + off);
                ldm_x4(alo[mt], bXlo + off);
            }
            uint32_t bhi[4][2], blo[4][2];
#pragma unroll
            for (int nt = 0; nt < 4; nt++) {
                int r = wn * 32 + nt * 8 + b_row;
                uint32_t off = r * ROWB + (ks * 2 + b_uoff) * 16;
                ldm_x2(bhi[nt], bWhi + off);
                ldm_x2(blo[nt], bWlo + off);
            }
#pragma unroll
            for (int mt = 0; mt < 4; mt++)
#pragma unroll
                for (int nt = 0; nt < 4; nt++) {
                    mma16816(acc[mt][nt], ahi[mt], bhi[nt]);
                    mma16816(acc[mt][nt], ahi[mt], blo[nt]);
                    mma16816(acc[mt][nt], alo[mt], bhi[nt]);
                }
        }
        __syncthreads();
    }

    int g = lane >> 2, tg = lane & 3;
#pragma unroll
    for (int mt = 0; mt < 4; mt++) {
        int r0 = n0 + wm * 64 + mt * 16 + g;
#pragma unroll
        for (int nt = 0; nt < 4; nt++) {
            int c = m0 + wn * 32 + nt * 8 + tg * 2;
            float b0 = bias[c], b1 = bias[c + 1];
            *(float2*)(g_qkv + r0 * M3_ + c) =
                make_float2(acc[mt][nt][0] + b0, acc[mt][nt][1] + b1);
            *(float2*)(g_qkv + (r0 + 8) * M3_ + c) =
                make_float2(acc[mt][nt][2] + b0, acc[mt][nt][3] + b1);
        }
    }
}

// ---------------- Kernel 2: causal flash attention via mma.sync bf16 hi/lo ----------------
// 128 threads (4 warps); warp w owns q-rows 16w..16w+15, full 64 cols.
#define FROWB 144   // 64 bf16 (128B) + 16B pad: ldmatrix conflict-free

__global__ void __launch_bounds__(128) flash_mma_kernel()
{
    __shared__ __align__(16) char sKhi[64 * FROWB];
    __shared__ __align__(16) char sKlo[64 * FROWB];
    __shared__ __align__(16) char sVhi[64 * FROWB];
    __shared__ __align__(16) char sVlo[64 * FROWB];

    int qt = 15 - blockIdx.x;          // heavy blocks first
    int bh = blockIdx.y;
    int b = bh >> 4, h = bh & 15;
    int tid = threadIdx.x;
    int w = tid >> 5, lane = tid & 31;
    int g = lane >> 2, c4 = lane & 3;

    uint32_t bKhi = smem_u32(sKhi), bKlo = smem_u32(sKlo);
    uint32_t bVhi = smem_u32(sVhi), bVlo = smem_u32(sVlo);

    // ---- stage Q (hi/lo) in sK buffers, extract A-fragments into registers ----
    for (int l = tid; l < 2048; l += 128) {
        int r = l >> 5, d2 = l & 31;
        const float2 q2 = *(const float2*)(g_qkv + (b * T_ + qt * 64 + r) * M3_ + h * 64 + d2 * 2);
        __nv_bfloat16 h0 = __float2bfloat16(q2.x);
        __nv_bfloat16 h1 = __float2bfloat16(q2.y);
        float f0 = q2.x - __bfloat162float(h0);
        float f1 = q2.y - __bfloat162float(h1);
        *(uint32_t*)(sKhi + r * FROWB + d2 * 4) = pack_bf16(__bfloat162float(h0), __bfloat162float(h1));
        *(uint32_t*)(sKlo + r * FROWB + d2 * 4) = pack_bf16(f0, f1);
    }
    __syncthreads();

    int a_mat = lane >> 3, a_row = lane & 7;
    int a_roff = ((a_mat & 1) << 3) + a_row;
    int a_uoff = a_mat >> 1;
    uint32_t qhi[4][4], qlo[4][4];
#pragma unroll
    for (int kc = 0; kc < 4; kc++) {
        uint32_t off = (w * 16 + a_roff) * FROWB + (kc * 2 + a_uoff) * 16;
        ldm_x4(qhi[kc], bKhi + off);
        ldm_x4(qlo[kc], bKlo + off);
    }

    float o[8][4];
#pragma unroll
    for (int et = 0; et < 8; et++)
#pragma unroll
        for (int k = 0; k < 4; k++) o[et][k] = 0.f;
    float m0 = -1e30f, m1 = -1e30f, l0s = 0.f, l1s = 0.f;

    int b_row = lane & 7;
    int b_uoff = (lane >> 3) & 1;
    int row0 = w * 16 + g, row1 = row0 + 8;

    for (int kt = 0; kt <= qt; kt++) {
        __syncthreads();   // previous iter's ldmatrix reads done
        for (int l = tid; l < 2048; l += 128) {
            int r = l >> 5, d2 = l & 31;
            const float* base = g_qkv + (b * T_ + kt * 64 + r) * M3_ + h * 64 + d2 * 2;
            float2 k2 = *(const float2*)(base + C_);
            float2 v2 = *(const float2*)(base + 2 * C_);
            __nv_bfloat16 kh0 = __float2bfloat16(k2.x), kh1 = __float2bfloat16(k2.y);
            __nv_bfloat16 vh0 = __float2bfloat16(v2.x), vh1 = __float2bfloat16(v2.y);
            *(uint32_t*)(sKhi + r * FROWB + d2 * 4) = pack_bf16(__bfloat162float(kh0), __bfloat162float(kh1));
            *(uint32_t*)(sKlo + r * FROWB + d2 * 4) =
                pack_bf16(k2.x - __bfloat162float(kh0), k2.y - __bfloat162float(kh1));
            *(uint32_t*)(sVhi + r * FROWB + d2 * 4) = pack_bf16(__bfloat162float(vh0), __bfloat162float(vh1));
            *(uint32_t*)(sVlo + r * FROWB + d2 * 4) =
                pack_bf16(v2.x - __bfloat162float(vh0), v2.y - __bfloat162float(vh1));
        }
        __syncthreads();

        // ---- scores 16x64 per warp ----
        float sc[8][4];
#pragma unroll
        for (int nt = 0; nt < 8; nt++)
#pragma unroll
            for (int k = 0; k < 4; k++) sc[nt][k] = 0.f;
#pragma unroll
        for (int nt = 0; nt < 8; nt++) {
#pragma unroll
            for (int kc = 0; kc < 4; kc++) {
                uint32_t kh[2], kl[2];
                uint32_t off = (nt * 8 + b_row) * FROWB + (kc * 2 + b_uoff) * 16;
                ldm_x2(kh, bKhi + off);
                ldm_x2(kl, bKlo + off);
                mma16816(sc[nt], qhi[kc], kh);
                mma16816(sc[nt], qhi[kc], kl);
                mma16816(sc[nt], qlo[kc], kh);
            }
        }

        // ---- scale + mask + online softmax ----
        bool diag = (kt == qt);
        float mloc0 = -1e30f, mloc1 = -1e30f;
#pragma unroll
        for (int nt = 0; nt < 8; nt++) {
            int col = nt * 8 + c4 * 2;
#pragma unroll
            for (int u = 0; u < 2; u++) {
                float s0 = sc[nt][u] * 0.125f;
                float s1 = sc[nt][2 + u] * 0.125f;
                if (diag && (col + u) > row0) s0 = -1e30f;
                if (diag && (col + u) > row1) s1 = -1e30f;
                sc[nt][u] = s0; sc[nt][2 + u] = s1;
                mloc0 = fmaxf(mloc0, s0);
                mloc1 = fmaxf(mloc1, s1);
            }
        }
        mloc0 = fmaxf(mloc0, __shfl_xor_sync(0xffffffffu, mloc0, 1));
        mloc0 = fmaxf(mloc0, __shfl_xor_sync(0xffffffffu, mloc0, 2));
        mloc1 = fmaxf(mloc1, __shfl_xor_sync(0xffffffffu, mloc1, 1));
        mloc1 = fmaxf(mloc1, __shfl_xor_sync(0xffffffffu, mloc1, 2));
        float mn0 = fmaxf(m0, mloc0), mn1 = fmaxf(m1, mloc1);
        float cr0 = __expf(m0 - mn0), cr1 = __expf(m1 - mn1);
        m0 = mn0; m1 = mn1;
        float ps0 = 0.f, ps1 = 0.f;
#pragma unroll
        for (int nt = 0; nt < 8; nt++) {
            sc[nt][0] = __expf(sc[nt][0] - mn0);
            sc[nt][1] = __expf(sc[nt][1] - mn0);
            sc[nt][2] = __expf(sc[nt][2] - mn1);
            sc[nt][3] = __expf(sc[nt][3] - mn1);
            ps0 += sc[nt][0] + sc[nt][1];
            ps1 += sc[nt][2] + sc[nt][3];
        }
        ps0 += __shfl_xor_sync(0xffffffffu, ps0, 1);
        ps0 += __shfl_xor_sync(0xffffffffu, ps0, 2);
        ps1 += __shfl_xor_sync(0xffffffffu, ps1, 1);
        ps1 += __shfl_xor_sync(0xffffffffu, ps1, 2);
        l0s = l0s * cr0 + ps0;
        l1s = l1s * cr1 + ps1;
#pragma unroll
        for (int et = 0; et < 8; et++) {
            o[et][0] *= cr0; o[et][1] *= cr0;
            o[et][2] *= cr1; o[et][3] *= cr1;
        }

        // ---- PV: P(C-layout) reused as A-fragments, V via ldmatrix.trans ----
#pragma unroll
        for (int jc = 0; jc < 4; jc++) {
            uint32_t phi[4], plo[4];
#pragma unroll
            for (int q = 0; q < 4; q++) {
                int nt = jc * 2 + (q >> 1);
                int u = (q & 1) * 2;
                float p0 = sc[nt][u], p1 = sc[nt][u + 1];
                __nv_bfloat16 b0 = __float2bfloat16(p0), b1 = __float2bfloat16(p1);
                int ai = (q >> 1) * 2 + (q & 1);
                phi[ai] = pack_bf16(__bfloat162float(b0), __bfloat162float(b1));
                plo[ai] = pack_bf16(p0 - __bfloat162float(b0), p1 - __bfloat162float(b1));
            }
#pragma unroll
            for (int et = 0; et < 8; et++) {
                uint32_t vh[2], vl[2];
                uint32_t off = (jc * 16 + (lane & 15)) * FROWB + et * 16;
                ldm_x2_trans(vh, bVhi + off);
                ldm_x2_trans(vl, bVlo + off);
                mma16816(o[et], phi, vh);
                mma16816(o[et], phi, vl);
                mma16816(o[et], plo, vh);
            }
        }
    }

    // ---- output ----
    float inv0 = 1.f / l0s, inv1 = 1.f / l1s;
    int r0g = b * T_ + qt * 64 + row0;
    int e0 = c4 * 2;
#pragma unroll
    for (int et = 0; et < 8; et++) {
        *(float2*)(g_ysharp + r0g * C_ + h * 64 + et * 8 + e0) =
            make_float2(o[et][0] * inv0, o[et][1] * inv0);
        *(float2*)(g_ysharp + (r0g + 8) * C_ + h * 64 + et * 8 + e0) =
            make_float2(o[et][2] * inv1, o[et][3] * inv1);
    }
}

// ---------------- Kernel 3a: per-chunk state contribution C = Kp^T @ V ----------------
__global__ void __launch_bounds__(256) chunk_state_kernel()
{
    __shared__ float KPT[64 * 65];
    __shared__ float V[64 * 64];

    int ch = blockIdx.x, bh = blockIdx.y;
    int b = bh >> 4, h = bh & 15;
    int tid = threadIdx.x;
    int d = tid >> 2, lane4 = tid & 3;

    for (int l = tid; l < 64 * 64; l += 256) {
        int r = l >> 6, dd = l & 63;
        int gidx = (b * T_ + ch * 64 + r) * M3_ + h * 64 + dd;
        KPT[dd * 65 + r] = elup(g_qkv[gidx + C_] * 0.125f);
        V[r * 64 + dd]   = g_qkv[gidx + 2 * C_];
    }
    __syncthreads();

    float acc[16];
#pragma unroll
    for (int e = 0; e < 16; e++) acc[e] = 0.f;
    float ks = 0.f;
    const float4* Vv = (const float4*)V;
#pragma unroll 8
    for (int j = 0; j < 64; j++) {
        float kp = KPT[d * 65 + j];
        ks += kp;
#pragma unroll
        for (int k = 0; k < 4; k++) {
            float4 vv = Vv[j * 16 + k * 4 + lane4];
            acc[k * 4 + 0] = fmaf(kp, vv.x, acc[k * 4 + 0]);
            acc[k * 4 + 1] = fmaf(kp, vv.y, acc[k * 4 + 1]);
            acc[k * 4 + 2] = fmaf(kp, vv.z, acc[k * 4 + 2]);
            acc[k * 4 + 3] = fmaf(kp, vv.w, acc[k * 4 + 3]);
        }
    }
    float* cs = g_cs + (bh * 16 + ch) * 4096 + d * 64;
#pragma unroll
    for (int k = 0; k < 4; k++)
        *(float4*)(cs + k * 16 + lane4 * 4) =
            make_float4(acc[k * 4 + 0], acc[k * 4 + 1], acc[k * 4 + 2], acc[k * 4 + 3]);
    if (lane4 == 0) g_ck[(bh * 16 + ch) * 64 + d] = ks;
}

// ---------------- Kernel 3b: exclusive prefix over chunks ----------------
__global__ void __launch_bounds__(256) prefix_kernel()
{
    int bh = blockIdx.x;
    for (int idx = threadIdx.x; idx < 4096; idx += 256) {
        float run = 0.f;
#pragma unroll
        for (int ch = 0; ch < 16; ch++) {
            int o = (bh * 16 + ch) * 4096 + idx;
            g_sprev[o] = run;
            run += g_cs[o];
        }
    }
    if (threadIdx.x < 64) {
        int idx = threadIdx.x;
        float run = 0.f;
#pragma unroll
        for (int ch = 0; ch < 16; ch++) {
            int o = (bh * 16 + ch) * 64 + idx;
            g_ckprev[o] = run;
            run += g_ck[o];
        }
    }
}

// ---------------- Kernel 3c: linear attention output (fully parallel) ----------------
__global__ void __launch_bounds__(256) linear_out_kernel()
{
    extern __shared__ float sm[];
    float* QP = sm;                // 64 x 65
    float* KP = QP + 64 * 65;      // 64 x 64 (swizzled)
    float* V  = KP + 64 * 64;      // 64 x 64
    float* P  = V + 64 * 64;       // 64 x 65
    float* SP = P + 64 * 65;       // 64 x 68
    float* kc = SP + 64 * 68;      // 64

    int ch = blockIdx.x, bh = blockIdx.y;
    int b = bh >> 4, h = bh & 15;
    int tid = threadIdx.x;
    int i = tid >> 2, lane4 = tid & 3;

    for (int l = tid; l < 64 * 64; l += 256) {
        int r = l >> 6, d = l & 63;
        int gidx = (b * T_ + ch * 64 + r) * M3_ + h * 64 + d;
        QP[r * 65 + d] = elup(g_qkv[gidx] * 0.125f);
        int d4 = d >> 2;
        KP[r * 64 + ((d4 ^ (r & 3)) << 2) + (d & 3)] = elup(g_qkv[gidx + C_] * 0.125f);
        V[r * 64 + d] = g_qkv[gidx + 2 * C_];
        SP[r * 68 + d] = g_sprev[(bh * 16 + ch) * 4096 + r * 64 + d];
    }
    if (tid < 64) kc[tid] = g_ckprev[(bh * 16 + ch) * 64 + tid];
    __syncthreads();

    float s[16];
#pragma unroll
    for (int jj = 0; jj < 16; jj++) s[jj] = 0.f;
    const float4* Kv = (const float4*)KP;
#pragma unroll
    for (int d4 = 0; d4 < 16; d4++) {
        float q0 = QP[i * 65 + 4 * d4 + 0];
        float q1 = QP[i * 65 + 4 * d4 + 1];
        float q2 = QP[i * 65 + 4 * d4 + 2];
        float q3 = QP[i * 65 + 4 * d4 + 3];
#pragma unroll
        for (int jj = 0; jj < 16; jj++) {
            int j = 4 * jj + lane4;
            float4 kv = Kv[j * 16 + (d4 ^ lane4)];
            s[jj] += q0 * kv.x + q1 * kv.y + q2 * kv.z + q3 * kv.w;
        }
    }
    float psum = 0.f;
#pragma unroll
    for (int jj = 0; jj < 16; jj++) {
        int j = 4 * jj + lane4;
        float sv = (j <= i) ? s[jj] : 0.f;
        P[i * 65 + j] = sv;
        psum += sv;
    }
    float dpart = 0.f;
#pragma unroll
    for (int dd = 0; dd < 16; dd++)
        dpart += QP[i * 65 + lane4 * 16 + dd] * kc[lane4 * 16 + dd];
    float den = psum + dpart;
    den += __shfl_xor_sync(0xffffffffu, den, 1);
    den += __shfl_xor_sync(0xffffffffu, den, 2);
    den += 1e-4f;

    float num[16];
#pragma unroll
    for (int e = 0; e < 16; e++) num[e] = 0.f;
    const float4* SPv = (const float4*)SP;
#pragma unroll 8
    for (int d = 0; d < 64; d++) {
        float q = QP[i * 65 + d];
#pragma unroll
        for (int k = 0; k < 4; k++) {
            float4 sp = SPv[d * 17 + k * 4 + lane4];
            num[k * 4 + 0] = fmaf(q, sp.x, num[k * 4 + 0]);
            num[k * 4 + 1] = fmaf(q, sp.y, num[k * 4 + 1]);
            num[k * 4 + 2] = fmaf(q, sp.z, num[k * 4 + 2]);
            num[k * 4 + 3] = fmaf(q, sp.w, num[k * 4 + 3]);
        }
    }
    __syncwarp();
    const float4* Vv = (const float4*)V;
#pragma unroll 8
    for (int j = 0; j < 64; j++) {
        float pv = P[i * 65 + j];
#pragma unroll
        for (int k = 0; k < 4; k++) {
            float4 vv = Vv[j * 16 + k * 4 + lane4];
            num[k * 4 + 0] = fmaf(pv, vv.x, num[k * 4 + 0]);
            num[k * 4 + 1] = fmaf(pv, vv.y, num[k * 4 + 1]);
            num[k * 4 + 2] = fmaf(pv, vv.z, num[k * 4 + 2]);
            num[k * 4 + 3] = fmaf(pv, vv.w, num[k * 4 + 3]);
        }
    }
    float invd = 1.f / den;
    float* orow = g_ylin + (b * T_ + ch * 64 + i) * C_ + h * 64;
#pragma unroll
    for (int k = 0; k < 4; k++)
        *(float4*)(orow + k * 16 + lane4 * 4) =
            make_float4(num[k * 4 + 0] * invd, num[k * 4 + 1] * invd,
                        num[k * 4 + 2] * invd, num[k * 4 + 3] * invd);
}

// ---------------- Kernel 4: combine (vectorized float4) ----------------
__device__ __forceinline__ void block_ln_stats(float lsum, float lsq, float* red,
                                               float* mean, float* rstd)
{
#pragma unroll
    for (int m = 16; m >= 1; m >>= 1) {
        lsum += __shfl_xor_sync(0xffffffffu, lsum, m);
        lsq  += __shfl_xor_sync(0xffffffffu, lsq, m);
    }
    int w = threadIdx.x >> 5;
    if ((threadIdx.x & 31) == 0) { red[w] = lsum; red[8 + w] = lsq; }
    __syncthreads();
    if (threadIdx.x == 0) {
        float s = 0.f, q = 0.f;
#pragma unroll
        for (int k = 0; k < 8; k++) { s += red[k]; q += red[8 + k]; }
        float mu = s * (1.f / 1024.f);
        red[16] = mu;
        red[17] = rsqrtf(q * (1.f / 1024.f) - mu * mu + 1e-5f);
    }
    __syncthreads();
    *mean = red[16];
    *rstd = red[17];
}

__global__ void __launch_bounds__(256) combine_kernel(
    const float* __restrict__ fg,
    const float* __restrict__ attn_g, const float* __restrict__ attn_b,
    const float* __restrict__ out_g,  const float* __restrict__ out_b,
    const float* __restrict__ pre_g,  const float* __restrict__ pre_b,
    const float* __restrict__ bw,     const float* __restrict__ wrow,
    const float* __restrict__ wcol,   const float* __restrict__ palpha,
    const float* __restrict__ pbias,  float* __restrict__ out)
{
    __shared__ float sx[1024];
    __shared__ float sy[1024];
    __shared__ float sz[1024];
    __shared__ float red[32];

    int n = blockIdx.x, tid = threadIdx.x;
    int c0 = tid * 4;
    float afg = 1.f / (1.f + __expf(-fg[0]));

    float4 ylv = *(const float4*)(g_ylin + n * C_ + c0);
    float4 ysv = *(const float4*)(g_ysharp + n * C_ + c0);
    float yl[4] = {ylv.x, ylv.y, ylv.z, ylv.w};
    float ys[4] = {ysv.x, ysv.y, ysv.z, ysv.w};
    float yv[4];
    float hsum = 0.f, hsq = 0.f;
#pragma unroll
    for (int k = 0; k < 4; k++) { hsum += yl[k]; hsq += yl[k] * yl[k]; }
#pragma unroll
    for (int m = 1; m < 16; m <<= 1) {
        hsum += __shfl_xor_sync(0xffffffffu, hsum, m);
        hsq  += __shfl_xor_sync(0xffffffffu, hsq, m);
    }
    float hmean = hsum * (1.f / 64.f);
    float hrstd = rsqrtf(hsq * (1.f / 64.f) - hmean * hmean + 1e-5f);
#pragma unroll
    for (int k = 0; k < 4; k++) {
        int d = (c0 + k) & 63;
        float v = (yl[k] - hmean) * hrstd * attn_g[d] + attn_b[d];
        yv[k] = afg * ys[k] + (1.f - afg) * v;
    }

    float lsum = 0.f, lsq = 0.f;
#pragma unroll
    for (int k = 0; k < 4; k++) { lsum += yv[k]; lsq += yv[k] * yv[k]; }
    float mu, rs;
    block_ln_stats(lsum, lsq, red, &mu, &rs);
#pragma unroll
    for (int k = 0; k < 4; k++)
        yv[k] = (yv[k] - mu) * rs * out_g[c0 + k] + out_b[c0 + k];

    lsum = 0.f; lsq = 0.f;
#pragma unroll
    for (int k = 0; k < 4; k++) { lsum += yv[k]; lsq += yv[k] * yv[k]; }
    block_ln_stats(lsum, lsq, red, &mu, &rs);
#pragma unroll
    for (int k = 0; k < 4; k++)
        sx[c0 + k] = (yv[k] - mu) * rs * pre_g[c0 + k] + pre_b[c0 + k];
    __syncthreads();

    const float4* sx4 = (const float4*)sx;

    int g = c0 >> 4, j0 = c0 & 15;
    float4 ymv = make_float4(0.f, 0.f, 0.f, 0.f);
#pragma unroll
    for (int ii4 = 0; ii4 < 4; ii4++) {
        float4 sxv = sx4[g * 4 + ii4];
        float sxe[4] = {sxv.x, sxv.y, sxv.z, sxv.w};
#pragma unroll
        for (int t = 0; t < 4; t++) {
            int ii = ii4 * 4 + t;
            float4 bwv = *(const float4*)(bw + g * 256 + ii * 16 + j0);
            ymv.x = fmaf(sxe[t], bwv.x, ymv.x);
            ymv.y = fmaf(sxe[t], bwv.y, ymv.y);
            ymv.z = fmaf(sxe[t], bwv.z, ymv.z);
            ymv.w = fmaf(sxe[t], bwv.w, ymv.w);
        }
    }

    int gi = c0 >> 5, cc0 = c0 & 31;
    float4 zvv = make_float4(0.f, 0.f, 0.f, 0.f);
#pragma unroll
    for (int jj4 = 0; jj4 < 8; jj4++) {
        float4 sxv = sx4[gi * 8 + jj4];
        float sxe[4] = {sxv.x, sxv.y, sxv.z, sxv.w};
#pragma unroll
        for (int t = 0; t < 4; t++) {
            int jj = jj4 * 4 + t;
            float4 wcv = *(const float4*)(wcol + jj * 32 + cc0);
            zvv.x = fmaf(sxe[t], wcv.x, zvv.x);
            zvv.y = fmaf(sxe[t], wcv.y, zvv.y);
            zvv.z = fmaf(sxe[t], wcv.z, zvv.z);
            zvv.w = fmaf(sxe[t], wcv.w, zvv.w);
        }
    }
    *(float4*)(sy + c0) = ymv;
    *(float4*)(sz + c0) = zvv;
    __syncthreads();

    const float4* sz4 = (const float4*)sz;
    int r0 = c0 & 31;
    float zz[4] = {0.f, 0.f, 0.f, 0.f};
#pragma unroll
    for (int cc4 = 0; cc4 < 8; cc4++) {
        float4 szv = sz4[gi * 8 + cc4];
#pragma unroll
        for (int k = 0; k < 4; k++) {
            float4 wrv = *(const float4*)(wrow + (r0 + k) * 32 + cc4 * 4);
            zz[k] += szv.x * wrv.x + szv.y * wrv.y + szv.z * wrv.z + szv.w * wrv.w;
        }
    }

    float pa = palpha[0];
    float4 pbv = *(const float4*)(pbias + c0);
    float pbe[4] = {pbv.x, pbv.y, pbv.z, pbv.w};
#pragma unroll
    for (int k = 0; k < 4; k++) {
        int c = c0 + k;
        out[n * C_ + c] = sy[1023 - c] + pa * zz[k] + pbe[k];
    }
}

// ---------------- launch ----------------
extern "C" void kernel_launch(void* const* d_in, const int* in_sizes, int n_in,
                              void* d_out, int out_size)
{
    const float* x      = (const float*)d_in[0];
    const float* w      = (const float*)d_in[1];
    const float* cb     = (const float*)d_in[2];
    const float* fg     = (const float*)d_in[3];
    const float* ag     = (const float*)d_in[4];
    const float* ab     = (const float*)d_in[5];
    const float* og     = (const float*)d_in[6];
    const float* ob     = (const float*)d_in[7];
    const float* pg     = (const float*)d_in[8];
    const float* pb     = (const float*)d_in[9];
    const float* bw     = (const float*)d_in[10];
    const float* wrow   = (const float*)d_in[11];
    const float* wcol   = (const float*)d_in[12];
    const float* palpha = (const float*)d_in[13];
    const float* pbias  = (const float*)d_in[14];
    float* out = (float*)d_out;

    const int LINOUT_SMEM = (64 * 65 + 64 * 64 + 64 * 64 + 64 * 65 + 64 * 68 + 64) * 4; // 83712
    cudaFuncSetAttribute(linear_out_kernel, cudaFuncAttributeMaxDynamicSharedMemorySize, LINOUT_SMEM);

    split_kernel<<<1024, 256>>>(x, w);
    qkv_mma_kernel<<<dim3(M3_ / 128, NROW_ / 128), 256>>>(cb);
    flash_mma_kernel<<<dim3(16, 32), 128>>>();
    chunk_state_kernel<<<dim3(16, 32), 256>>>();
    prefix_kernel<<<32, 256>>>();
    linear_out_kernel<<<dim3(16, 32), 256, LINOUT_SMEM>>>();
    combine_kernel<<<NROW_, 256>>>(fg, ag, ab, og, ob, pg, pb, bw, wrow, wcol,
                                   palpha, pbias, out);
}